// round 2
// baseline (speedup 1.0000x reference)
#include <cuda_runtime.h>

// Problem constants
#define BB   2
#define TT_  2048
#define DD   1024
#define HH   16
#define HD   64
#define ROWS (BB * TT_)               // 4096
#define BTD  (ROWS * DD)              // 4194304
#define BHTT (134217728LL)            // B*H*T*T

// Scratch (allocation-free rule: __device__ globals)
__device__ float g_xn[ROWS * DD];
__device__ float g_qkv[ROWS * 3 * DD];
__device__ float g_qkv2[ROWS * 3 * DD];
__device__ float g_ctx[ROWS * DD];
__device__ float g_scores[134217728ULL];

__device__ __forceinline__ float warp_sum(float v) {
    #pragma unroll
    for (int o = 16; o; o >>= 1) v += __shfl_xor_sync(0xffffffffu, v, o);
    return v;
}
__device__ __forceinline__ float warp_max(float v) {
    #pragma unroll
    for (int o = 16; o; o >>= 1) v = fmaxf(v, __shfl_xor_sync(0xffffffffu, v, o));
    return v;
}

// ---------------- LayerNorm: one block per row of 1024 ----------------
__global__ void ln_kernel(const float* __restrict__ x, const float* __restrict__ gamma,
                          const float* __restrict__ beta, float* __restrict__ out) {
    int row = blockIdx.x;
    int tid = threadIdx.x;  // 256 threads, 4 floats each
    const float4 v = ((const float4*)(x + (size_t)row * DD))[tid];
    float s  = v.x + v.y + v.z + v.w;
    float s2 = v.x * v.x + v.y * v.y + v.z * v.z + v.w * v.w;
    __shared__ float red[16];
    s = warp_sum(s); s2 = warp_sum(s2);
    if ((tid & 31) == 0) { red[tid >> 5] = s; red[(tid >> 5) + 8] = s2; }
    __syncthreads();
    float ts = 0.f, ts2 = 0.f;
    #pragma unroll
    for (int i = 0; i < 8; i++) { ts += red[i]; ts2 += red[i + 8]; }
    float mu  = ts / (float)DD;
    float var = ts2 / (float)DD - mu * mu;
    float rstd = 1.0f / sqrtf(var + 1e-5f);
    const float4 gm = ((const float4*)gamma)[tid];
    const float4 bt = ((const float4*)beta)[tid];
    float4 o;
    o.x = (v.x - mu) * rstd * gm.x + bt.x;
    o.y = (v.y - mu) * rstd * gm.y + bt.y;
    o.z = (v.z - mu) * rstd * gm.z + bt.z;
    o.w = (v.w - mu) * rstd * gm.w + bt.w;
    ((float4*)(out + (size_t)row * DD))[tid] = o;
}

// ---------------- RoPE (in-place on q,k parts of qkv buffer) ----------------
__global__ void rope_kernel(float* __restrict__ qkv) {
    int row = blockIdx.x;
    int t = row & (TT_ - 1);
    int h = threadIdx.x >> 5;   // 16 heads
    int i = threadIdx.x & 31;   // half-dim index
    float invf = expf(-logf(10000.0f) * (2.0f * (float)i) / 64.0f);
    float ang = (float)t * invf;
    float s, c;
    sincosf(ang, &s, &c);
    float* p = qkv + (size_t)row * 3072 + h * 64;   // q
    float x1 = p[i], x2 = p[i + 32];
    p[i]      = x1 * c - x2 * s;
    p[i + 32] = x2 * c + x1 * s;
    float* pk = p + 1024;                            // k
    x1 = pk[i]; x2 = pk[i + 32];
    pk[i]      = x1 * c - x2 * s;
    pk[i + 32] = x2 * c + x1 * s;
}

// ---------------- SGEMM (NT): C[m,n] = sum_k A[m,k]*B[n,k] (+bias[n]) (+res[m,n])
// 128x128x8 tile, 256 threads, 8x8 per-thread microtile. z-batched via strides.
__global__ void __launch_bounds__(256)
sgemm_nt_kernel(const float* __restrict__ A, int lda, long long sAz,
                const float* __restrict__ B, int ldb, long long sBz,
                float* __restrict__ C, int ldc, long long sCz,
                const float* __restrict__ bias,
                const float* __restrict__ res,
                int K) {
    __shared__ float As[8][128];
    __shared__ float Bs[8][128];
    A += (long long)blockIdx.z * sAz;
    B += (long long)blockIdx.z * sBz;
    C += (long long)blockIdx.z * sCz;

    const int tid = threadIdx.x;
    const int m0 = blockIdx.y * 128;
    const int n0 = blockIdx.x * 128;
    const int lr = tid >> 1;
    const int lk = (tid & 1) * 4;
    const float* Ap = A + (size_t)(m0 + lr) * lda + lk;
    const float* Bp = B + (size_t)(n0 + lr) * ldb + lk;
    const int tx = tid & 15, ty = tid >> 4;

    float acc[8][8];
    #pragma unroll
    for (int i = 0; i < 8; i++)
        #pragma unroll
        for (int j = 0; j < 8; j++) acc[i][j] = 0.f;

    for (int k0 = 0; k0 < K; k0 += 8) {
        float4 a4 = *(const float4*)(Ap + k0);
        float4 b4 = *(const float4*)(Bp + k0);
        __syncthreads();
        As[lk + 0][lr] = a4.x; As[lk + 1][lr] = a4.y;
        As[lk + 2][lr] = a4.z; As[lk + 3][lr] = a4.w;
        Bs[lk + 0][lr] = b4.x; Bs[lk + 1][lr] = b4.y;
        Bs[lk + 2][lr] = b4.z; Bs[lk + 3][lr] = b4.w;
        __syncthreads();
        #pragma unroll
        for (int kk = 0; kk < 8; kk++) {
            float4 a0 = *(const float4*)&As[kk][ty * 4];
            float4 a1 = *(const float4*)&As[kk][64 + ty * 4];
            float4 b0 = *(const float4*)&Bs[kk][tx * 4];
            float4 b1 = *(const float4*)&Bs[kk][64 + tx * 4];
            float ar[8] = {a0.x, a0.y, a0.z, a0.w, a1.x, a1.y, a1.z, a1.w};
            float br[8] = {b0.x, b0.y, b0.z, b0.w, b1.x, b1.y, b1.z, b1.w};
            #pragma unroll
            for (int i = 0; i < 8; i++)
                #pragma unroll
                for (int j = 0; j < 8; j++)
                    acc[i][j] += ar[i] * br[j];
        }
    }

    #pragma unroll
    for (int pm = 0; pm < 2; pm++)
        #pragma unroll
        for (int i = 0; i < 4; i++) {
            int m = m0 + pm * 64 + ty * 4 + i;
            float* crow = C + (size_t)m * ldc;
            #pragma unroll
            for (int pn = 0; pn < 2; pn++) {
                int n = n0 + pn * 64 + tx * 4;
                float4 cv;
                cv.x = acc[pm * 4 + i][pn * 4 + 0];
                cv.y = acc[pm * 4 + i][pn * 4 + 1];
                cv.z = acc[pm * 4 + i][pn * 4 + 2];
                cv.w = acc[pm * 4 + i][pn * 4 + 3];
                if (bias) {
                    const float4 bv = *(const float4*)(bias + n);
                    cv.x += bv.x; cv.y += bv.y; cv.z += bv.z; cv.w += bv.w;
                }
                if (res) {
                    const float4 rv = *(const float4*)(res + (size_t)m * ldc + n);
                    cv.x += rv.x; cv.y += rv.y; cv.z += rv.z; cv.w += rv.w;
                }
                *(float4*)(crow + n) = cv;
            }
        }
}

// ---------------- Scores: S[bh, t, s] = scale * q2 . k2, s<=t only ----------------
// blockIdx: x = s-tile, y = t-tile, z = bh. 64x64 tile, K=64.
__global__ void __launch_bounds__(256)
scores_kernel(const float* __restrict__ qkv2, float* __restrict__ scores) {
    const int st = blockIdx.x, tt = blockIdx.y;
    if (st > tt) return;
    const int bh = blockIdx.z;
    const int b = bh >> 4, h = bh & 15;

    __shared__ float Qs[64][68];
    __shared__ float Ks[64][68];
    const int tid = threadIdx.x;
    const float scale = 0.125f;  // 64^-0.5

    size_t qbase = ((size_t)b * TT_ + (size_t)tt * 64) * 3072 + h * 64;          // q2
    size_t kbase = ((size_t)b * TT_ + (size_t)st * 64) * 3072 + 1024 + h * 64;   // k2
    #pragma unroll
    for (int r = 0; r < 4; r++) {
        int idx = tid + r * 256;       // float4 unit, 0..1023
        int i = idx >> 4;              // row 0..63
        int d0 = (idx & 15) * 4;
        float4 qv = *(const float4*)(qkv2 + qbase + (size_t)i * 3072 + d0);
        Qs[d0 + 0][i] = qv.x * scale; Qs[d0 + 1][i] = qv.y * scale;
        Qs[d0 + 2][i] = qv.z * scale; Qs[d0 + 3][i] = qv.w * scale;
        float4 kv = *(const float4*)(qkv2 + kbase + (size_t)i * 3072 + d0);
        Ks[d0 + 0][i] = kv.x; Ks[d0 + 1][i] = kv.y;
        Ks[d0 + 2][i] = kv.z; Ks[d0 + 3][i] = kv.w;
    }
    __syncthreads();

    const int tx = tid & 15, ty = tid >> 4;
    float acc[4][4] = {};
    #pragma unroll
    for (int d = 0; d < 64; d++) {
        float4 a = *(const float4*)&Qs[d][ty * 4];
        float4 bq = *(const float4*)&Ks[d][tx * 4];
        float ar[4] = {a.x, a.y, a.z, a.w};
        float br[4] = {bq.x, bq.y, bq.z, bq.w};
        #pragma unroll
        for (int i = 0; i < 4; i++)
            #pragma unroll
            for (int j = 0; j < 4; j++)
                acc[i][j] += ar[i] * br[j];
    }

    long long sbase = ((long long)bh * TT_ + (long long)tt * 64) * TT_ + (long long)st * 64;
    #pragma unroll
    for (int i = 0; i < 4; i++) {
        int trow = tt * 64 + ty * 4 + i;
        #pragma unroll
        for (int j = 0; j < 4; j++) {
            int scol = st * 64 + tx * 4 + j;
            if (scol <= trow)
                scores[sbase + (long long)(ty * 4 + i) * TT_ + tx * 4 + j] = acc[i][j];
        }
    }
}

// ---------------- Causal softmax per row; zero-fills masked region ----------------
__global__ void softmax_kernel(const float* __restrict__ scores, float* __restrict__ probs) {
    long long row = blockIdx.x;            // bh*T + t
    int t = (int)(row & (TT_ - 1));
    const float* src = scores + row * TT_;
    float* dst = probs + row * TT_;
    int n = t + 1;
    int tid = threadIdx.x;

    float m = -1e30f;
    for (int s = tid; s < n; s += 256) m = fmaxf(m, src[s]);
    __shared__ float redm[8];
    __shared__ float reds[8];
    m = warp_max(m);
    if ((tid & 31) == 0) redm[tid >> 5] = m;
    __syncthreads();
    float bm = -1e30f;
    #pragma unroll
    for (int i = 0; i < 8; i++) bm = fmaxf(bm, redm[i]);

    float sum = 0.f;
    for (int s = tid; s < n; s += 256) {
        float e = expf(src[s] - bm);
        dst[s] = e;
        sum += e;
    }
    sum = warp_sum(sum);
    if ((tid & 31) == 0) reds[tid >> 5] = sum;
    __syncthreads();
    float bs = 0.f;
    #pragma unroll
    for (int i = 0; i < 8; i++) bs += reds[i];
    float inv = 1.0f / bs;
    for (int s = tid; s < n; s += 256) dst[s] *= inv;
    for (int s = n + tid; s < TT_; s += 256) dst[s] = 0.f;
}

// ---------------- ctx = P @ V per head, causal k-range ----------------
// blockIdx: x = t-tile (0..31), z = bh. Tile 64x64 (N=hD), BK=16.
__global__ void __launch_bounds__(256)
av_kernel(const float* __restrict__ probs, const float* __restrict__ qkv2,
          float* __restrict__ ctx) {
    const int tt = blockIdx.x;
    const int bh = blockIdx.z;
    const int b = bh >> 4, h = bh & 15;

    __shared__ float Ps[16][64];
    __shared__ float Vs[16][68];
    const int tid = threadIdx.x;
    const int tx = tid & 15, ty = tid >> 4;

    float acc[4][4] = {};
    long long pbase = ((long long)bh * TT_ + (long long)tt * 64) * TT_;
    size_t vbase = (size_t)b * TT_ * 3072 + 2048 + h * 64;

    const int i_ld = tid >> 2;         // P: row 0..63
    const int k_ld = (tid & 3) * 4;    // P: k 0,4,8,12
    const int r_ld = tid >> 4;         // V: row 0..15
    const int d_ld = (tid & 15) * 4;   // V: d

    const int kt_end = (tt + 1) * 4;
    for (int kt = 0; kt < kt_end; kt++) {
        int s0 = kt * 16;
        float4 pv = *(const float4*)(probs + pbase + (long long)i_ld * TT_ + s0 + k_ld);
        float4 vv = *(const float4*)(qkv2 + vbase + (size_t)(s0 + r_ld) * 3072 + d_ld);
        __syncthreads();
        Ps[k_ld + 0][i_ld] = pv.x; Ps[k_ld + 1][i_ld] = pv.y;
        Ps[k_ld + 2][i_ld] = pv.z; Ps[k_ld + 3][i_ld] = pv.w;
        *(float4*)&Vs[r_ld][d_ld] = vv;
        __syncthreads();
        #pragma unroll
        for (int k = 0; k < 16; k++) {
            float4 a = *(const float4*)&Ps[k][ty * 4];
            float4 bv = *(const float4*)&Vs[k][tx * 4];
            float ar[4] = {a.x, a.y, a.z, a.w};
            float br[4] = {bv.x, bv.y, bv.z, bv.w};
            #pragma unroll
            for (int i = 0; i < 4; i++)
                #pragma unroll
                for (int j = 0; j < 4; j++)
                    acc[i][j] += ar[i] * br[j];
        }
    }

    size_t cbase = ((size_t)b * TT_ + (size_t)tt * 64) * DD + h * 64;
    #pragma unroll
    for (int i = 0; i < 4; i++) {
        float4 cv;
        cv.x = acc[i][0]; cv.y = acc[i][1]; cv.z = acc[i][2]; cv.w = acc[i][3];
        *(float4*)(ctx + cbase + (size_t)(ty * 4 + i) * DD + tx * 4) = cv;
    }
}

// ---------------- Launch ----------------
extern "C" void kernel_launch(void* const* d_in, const int* in_sizes, int n_in,
                              void* d_out, int out_size) {
    const float* x      = (const float*)d_in[0];
    const float* w_in   = (const float*)d_in[1];
    const float* b_in   = (const float*)d_in[2];
    const float* w_out  = (const float*)d_in[3];
    const float* b_out  = (const float*)d_in[4];
    const float* gamma  = (const float*)d_in[5];
    const float* beta   = (const float*)d_in[6];
    float* out = (float*)d_out;

    float *xn, *qkv, *qkv2, *ctx, *scores;
    cudaGetSymbolAddress((void**)&xn, g_xn);
    cudaGetSymbolAddress((void**)&qkv, g_qkv);
    cudaGetSymbolAddress((void**)&qkv2, g_qkv2);
    cudaGetSymbolAddress((void**)&ctx, g_ctx);
    cudaGetSymbolAddress((void**)&scores, g_scores);

    // Output may be (out) only, or (out, attn_weights) concatenated.
    bool has_attn = ((long long)out_size >= (long long)BTD + BHTT);
    float* probs = has_attn ? (out + BTD) : scores;

    // 1. pre-LN
    ln_kernel<<<ROWS, 256>>>(x, gamma, beta, xn);
    // 2. fused QKV projection (+bias): [4096,1024] @ [3072,1024]^T
    sgemm_nt_kernel<<<dim3(24, 32, 1), 256>>>(xn, 1024, 0,
                                              w_in, 1024, 0,
                                              qkv, 3072, 0,
                                              b_in, nullptr, 1024);
    // 3. RoPE on q,k (in place)
    rope_kernel<<<ROWS, 512>>>(qkv);
    // 4. second projection (bias-free), z-batched over {q,k,v}
    sgemm_nt_kernel<<<dim3(8, 32, 3), 256>>>(qkv, 3072, 1024,
                                             w_in, 1024, 1024LL * 1024,
                                             qkv2, 3072, 1024,
                                             nullptr, nullptr, 1024);
    // 5. causal scores
    scores_kernel<<<dim3(32, 32, 32), 256>>>(qkv2, scores);
    // 6. softmax (writes probs; zero-fills masked region)
    softmax_kernel<<<BB * HH * TT_, 256>>>(scores, probs);
    // 7. ctx = P @ V
    av_kernel<<<dim3(32, 1, 32), 256>>>(probs, qkv2, ctx);
    // 8. out projection + bias + residual
    sgemm_nt_kernel<<<dim3(8, 32, 1), 256>>>(ctx, 1024, 0,
                                             w_out, 1024, 0,
                                             out, 1024, 0,
                                             b_out, x, 1024);
}

// round 5
// speedup vs baseline: 1.7699x; 1.7699x over previous
#include <cuda_runtime.h>
#include <cstdint>

// Problem constants
#define BB   2
#define TT_  2048
#define DD   1024
#define HH   16
#define ROWS (BB * TT_)               // 4096
#define BTD  (ROWS * DD)              // 4194304
#define BHTT 134217728LL              // B*H*T*T

// Scratch (allocation-free rule: __device__ globals)
__device__ float g_xn[ROWS * DD];
__device__ float g_qkv[ROWS * 3 * DD];
__device__ float g_qkv2[ROWS * 3 * DD];
__device__ float g_ctx[ROWS * DD];
__device__ float g_scores[134217728ULL];

__device__ __forceinline__ float warp_sum(float v) {
    #pragma unroll
    for (int o = 16; o; o >>= 1) v += __shfl_xor_sync(0xffffffffu, v, o);
    return v;
}
__device__ __forceinline__ float warp_max(float v) {
    #pragma unroll
    for (int o = 16; o; o >>= 1) v = fmaxf(v, __shfl_xor_sync(0xffffffffu, v, o));
    return v;
}

__device__ __forceinline__ uint32_t smem_u32(const void* p) {
    uint32_t a;
    asm("{ .reg .u64 t; cvta.to.shared.u64 t, %1; cvt.u32.u64 %0, t; }" : "=r"(a) : "l"(p));
    return a;
}
__device__ __forceinline__ uint32_t f2tf(float x) {
    uint32_t r;
    asm("cvt.rna.tf32.f32 %0, %1;" : "=r"(r) : "f"(x));
    return r;
}
__device__ __forceinline__ void mma_tf32(float* c, const uint32_t* a, const uint32_t* b) {
    asm volatile(
        "mma.sync.aligned.m16n8k8.row.col.f32.tf32.tf32.f32 "
        "{%0,%1,%2,%3}, {%4,%5,%6,%7}, {%8,%9}, {%0,%1,%2,%3};"
        : "+f"(c[0]), "+f"(c[1]), "+f"(c[2]), "+f"(c[3])
        : "r"(a[0]), "r"(a[1]), "r"(a[2]), "r"(a[3]), "r"(b[0]), "r"(b[1]));
}

// ======================= mma.sync tf32 NT GEMM =======================
// C[M,N] = A[M,K]*B[N,K]^T (+bias[n]) (+res[m,n]); A,B row-major K-contiguous.
// CTA tile 128x128, 256 threads = 8 warps (4m x 2n), warp tile 32x64.
// K staged 32/iter via cp.async double buffer; smem rows padded to 36 floats.

#define PADK   36
#define STGF   (128 * PADK)            // floats per matrix tile (4608)
#define STAGEF (2 * STGF)              // A+B per stage (9216 floats)
#define GSMEM  (2 * STAGEF * 4)        // 73728 bytes

__device__ __forceinline__ void load_stage(uint32_t sbase, int buf, int si,
                                           const float* __restrict__ A,
                                           const float* __restrict__ B,
                                           int lda, int ldb, int tid) {
    uint32_t as = sbase + (uint32_t)buf * (STAGEF * 4);
    uint32_t bs = as + STGF * 4;
    #pragma unroll
    for (int it = 0; it < 4; it++) {
        int idx = tid + it * 256;          // 0..1023 : 128 rows x 8 chunks
        int m = idx >> 3, kq = idx & 7;
        uint32_t off = (uint32_t)(m * PADK + kq * 4) * 4;
        const float* ag = A + (size_t)m * lda + si * 32 + kq * 4;
        const float* bg = B + (size_t)m * ldb + si * 32 + kq * 4;
        asm volatile("cp.async.cg.shared.global [%0], [%1], 16;"
                     :: "r"(as + off), "l"(ag) : "memory");
        asm volatile("cp.async.cg.shared.global [%0], [%1], 16;"
                     :: "r"(bs + off), "l"(bg) : "memory");
    }
    asm volatile("cp.async.commit_group;" ::: "memory");
}

__global__ void __launch_bounds__(256, 2)
tc_gemm_nt(const float* __restrict__ A, int lda, long long sAz,
           const float* __restrict__ B, int ldb, long long sBz,
           float* __restrict__ C, int ldc, long long sCz,
           const float* __restrict__ bias, const float* __restrict__ res,
           int K) {
    extern __shared__ float smf[];
    uint32_t sb = smem_u32(smf);
    A += (long long)blockIdx.z * sAz + (size_t)blockIdx.y * 128 * lda;
    B += (long long)blockIdx.z * sBz + (size_t)blockIdx.x * 128 * ldb;
    C += (long long)blockIdx.z * sCz;
    const int m0 = blockIdx.y * 128, n0 = blockIdx.x * 128;
    const int tid = threadIdx.x;
    const int lane = tid & 31, wid = tid >> 5;
    const int wm = wid & 3, wn = wid >> 2;
    const int r = lane >> 2, kg = lane & 3;

    float acc[2][8][4];
    #pragma unroll
    for (int mf = 0; mf < 2; mf++)
        #pragma unroll
        for (int nf = 0; nf < 8; nf++)
            #pragma unroll
            for (int i = 0; i < 4; i++) acc[mf][nf][i] = 0.f;

    const int nk = K >> 5;
    load_stage(sb, 0, 0, A, B, lda, ldb, tid);

    for (int s = 0; s < nk; s++) {
        __syncthreads();   // everyone done reading the buffer we are about to refill
        if (s + 1 < nk) {
            load_stage(sb, (s + 1) & 1, s + 1, A, B, lda, ldb, tid);
            asm volatile("cp.async.wait_group 1;" ::: "memory");
        } else {
            asm volatile("cp.async.wait_group 0;" ::: "memory");
        }
        __syncthreads();

        const float* as = smf + (s & 1) * STAGEF;
        const float* bs = as + STGF;
        const float* abase = as + (wm * 32 + r) * PADK + kg;
        const float* bbase = bs + (wn * 64 + r) * PADK + kg;
        #pragma unroll
        for (int kst = 0; kst < 4; kst++) {
            uint32_t a[2][4], b[8][2];
            #pragma unroll
            for (int mf = 0; mf < 2; mf++) {
                const float* p = abase + mf * 16 * PADK + kst * 8;
                a[mf][0] = f2tf(p[0]);
                a[mf][1] = f2tf(p[8 * PADK]);
                a[mf][2] = f2tf(p[4]);
                a[mf][3] = f2tf(p[8 * PADK + 4]);
            }
            #pragma unroll
            for (int nf = 0; nf < 8; nf++) {
                const float* p = bbase + nf * 8 * PADK + kst * 8;
                b[nf][0] = f2tf(p[0]);
                b[nf][1] = f2tf(p[4]);
            }
            #pragma unroll
            for (int mf = 0; mf < 2; mf++)
                #pragma unroll
                for (int nf = 0; nf < 8; nf++)
                    mma_tf32(acc[mf][nf], a[mf], b[nf]);
        }
    }

    // Epilogue: c0,c1 at (row, col..col+1), c2,c3 at (row+8, ...)
    #pragma unroll
    for (int mf = 0; mf < 2; mf++) {
        int row = m0 + wm * 32 + mf * 16 + r;
        #pragma unroll
        for (int half = 0; half < 2; half++) {
            int rr = row + half * 8;
            float* crow = C + (size_t)rr * ldc;
            const float* rrow = res ? res + (size_t)rr * ldc : nullptr;
            #pragma unroll
            for (int nf = 0; nf < 8; nf++) {
                int col = n0 + wn * 64 + nf * 8 + 2 * kg;
                float2 v;
                v.x = acc[mf][nf][half * 2 + 0];
                v.y = acc[mf][nf][half * 2 + 1];
                if (bias) {
                    v.x += bias[col];
                    v.y += bias[col + 1];
                }
                if (rrow) {
                    const float2 rv = *(const float2*)(rrow + col);
                    v.x += rv.x; v.y += rv.y;
                }
                *(float2*)(crow + col) = v;
            }
        }
    }
}

// ---------------- LayerNorm: one block per row of 1024 ----------------
__global__ void ln_kernel(const float* __restrict__ x, const float* __restrict__ gamma,
                          const float* __restrict__ beta, float* __restrict__ out) {
    int row = blockIdx.x;
    int tid = threadIdx.x;
    const float4 v = ((const float4*)(x + (size_t)row * DD))[tid];
    float s  = v.x + v.y + v.z + v.w;
    float s2 = v.x * v.x + v.y * v.y + v.z * v.z + v.w * v.w;
    __shared__ float red[16];
    s = warp_sum(s); s2 = warp_sum(s2);
    if ((tid & 31) == 0) { red[tid >> 5] = s; red[(tid >> 5) + 8] = s2; }
    __syncthreads();
    float ts = 0.f, ts2 = 0.f;
    #pragma unroll
    for (int i = 0; i < 8; i++) { ts += red[i]; ts2 += red[i + 8]; }
    float mu  = ts / (float)DD;
    float var = ts2 / (float)DD - mu * mu;
    float rstd = 1.0f / sqrtf(var + 1e-5f);
    const float4 gm = ((const float4*)gamma)[tid];
    const float4 bt = ((const float4*)beta)[tid];
    float4 o;
    o.x = (v.x - mu) * rstd * gm.x + bt.x;
    o.y = (v.y - mu) * rstd * gm.y + bt.y;
    o.z = (v.z - mu) * rstd * gm.z + bt.z;
    o.w = (v.w - mu) * rstd * gm.w + bt.w;
    ((float4*)(out + (size_t)row * DD))[tid] = o;
}

// ---------------- RoPE (in-place on q,k parts of qkv buffer) ----------------
__global__ void rope_kernel(float* __restrict__ qkv) {
    int row = blockIdx.x;
    int t = row & (TT_ - 1);
    int h = threadIdx.x >> 5;
    int i = threadIdx.x & 31;
    float invf = expf(-logf(10000.0f) * (2.0f * (float)i) / 64.0f);
    float ang = (float)t * invf;
    float s, c;
    sincosf(ang, &s, &c);
    float* p = qkv + (size_t)row * 3072 + h * 64;
    float x1 = p[i], x2 = p[i + 32];
    p[i]      = x1 * c - x2 * s;
    p[i + 32] = x2 * c + x1 * s;
    float* pk = p + 1024;
    x1 = pk[i]; x2 = pk[i + 32];
    pk[i]      = x1 * c - x2 * s;
    pk[i + 32] = x2 * c + x1 * s;
}

// ---------------- Scores: S[bh, t, s] = scale * q2 . k2, s<=t only ----------------
__global__ void __launch_bounds__(256)
scores_kernel(const float* __restrict__ qkv2, float* __restrict__ scores) {
    const int st = blockIdx.x, tt = blockIdx.y;
    if (st > tt) return;
    const int bh = blockIdx.z;
    const int b = bh >> 4, h = bh & 15;

    __shared__ float Qs[64][68];
    __shared__ float Ks[64][68];
    const int tid = threadIdx.x;
    const float scale = 0.125f;

    size_t qbase = ((size_t)b * TT_ + (size_t)tt * 64) * 3072 + h * 64;
    size_t kbase = ((size_t)b * TT_ + (size_t)st * 64) * 3072 + 1024 + h * 64;
    #pragma unroll
    for (int rr = 0; rr < 4; rr++) {
        int idx = tid + rr * 256;
        int i = idx >> 4;
        int d0 = (idx & 15) * 4;
        float4 qv = *(const float4*)(qkv2 + qbase + (size_t)i * 3072 + d0);
        Qs[d0 + 0][i] = qv.x * scale; Qs[d0 + 1][i] = qv.y * scale;
        Qs[d0 + 2][i] = qv.z * scale; Qs[d0 + 3][i] = qv.w * scale;
        float4 kv = *(const float4*)(qkv2 + kbase + (size_t)i * 3072 + d0);
        Ks[d0 + 0][i] = kv.x; Ks[d0 + 1][i] = kv.y;
        Ks[d0 + 2][i] = kv.z; Ks[d0 + 3][i] = kv.w;
    }
    __syncthreads();

    const int tx = tid & 15, ty = tid >> 4;
    float acc[4][4] = {};
    #pragma unroll
    for (int d = 0; d < 64; d++) {
        float4 a = *(const float4*)&Qs[d][ty * 4];
        float4 bq = *(const float4*)&Ks[d][tx * 4];
        float ar[4] = {a.x, a.y, a.z, a.w};
        float br[4] = {bq.x, bq.y, bq.z, bq.w};
        #pragma unroll
        for (int i = 0; i < 4; i++)
            #pragma unroll
            for (int j = 0; j < 4; j++)
                acc[i][j] += ar[i] * br[j];
    }

    long long sbase = ((long long)bh * TT_ + (long long)tt * 64) * TT_ + (long long)st * 64;
    #pragma unroll
    for (int i = 0; i < 4; i++) {
        int trow = tt * 64 + ty * 4 + i;
        #pragma unroll
        for (int j = 0; j < 4; j++) {
            int scol = st * 64 + tx * 4 + j;
            if (scol <= trow)
                scores[sbase + (long long)(ty * 4 + i) * TT_ + tx * 4 + j] = acc[i][j];
        }
    }
}

// ---------------- Causal softmax per row; zero-fills masked region ----------------
__global__ void softmax_kernel(const float* __restrict__ scores, float* __restrict__ probs) {
    long long row = blockIdx.x;
    int t = (int)(row & (TT_ - 1));
    const float* src = scores + row * TT_;
    float* dst = probs + row * TT_;
    int n = t + 1;
    int tid = threadIdx.x;

    float m = -1e30f;
    for (int s = tid; s < n; s += 256) m = fmaxf(m, src[s]);
    __shared__ float redm[8];
    __shared__ float reds[8];
    m = warp_max(m);
    if ((tid & 31) == 0) redm[tid >> 5] = m;
    __syncthreads();
    float bm = -1e30f;
    #pragma unroll
    for (int i = 0; i < 8; i++) bm = fmaxf(bm, redm[i]);

    float sum = 0.f;
    for (int s = tid; s < n; s += 256) {
        float e = expf(src[s] - bm);
        dst[s] = e;
        sum += e;
    }
    sum = warp_sum(sum);
    if ((tid & 31) == 0) reds[tid >> 5] = sum;
    __syncthreads();
    float bs = 0.f;
    #pragma unroll
    for (int i = 0; i < 8; i++) bs += reds[i];
    float inv = 1.0f / bs;
    for (int s = tid; s < n; s += 256) dst[s] *= inv;
    for (int s = n + tid; s < TT_; s += 256) dst[s] = 0.f;
}

// ---------------- ctx = P @ V per head, causal k-range ----------------
__global__ void __launch_bounds__(256)
av_kernel(const float* __restrict__ probs, const float* __restrict__ qkv2,
          float* __restrict__ ctx) {
    const int tt = blockIdx.x;
    const int bh = blockIdx.z;
    const int b = bh >> 4, h = bh & 15;

    __shared__ float Ps[16][64];
    __shared__ float Vs[16][68];
    const int tid = threadIdx.x;
    const int tx = tid & 15, ty = tid >> 4;

    float acc[4][4] = {};
    long long pbase = ((long long)bh * TT_ + (long long)tt * 64) * TT_;
    size_t vbase = (size_t)b * TT_ * 3072 + 2048 + h * 64;

    const int i_ld = tid >> 2;
    const int k_ld = (tid & 3) * 4;
    const int r_ld = tid >> 4;
    const int d_ld = (tid & 15) * 4;

    const int kt_end = (tt + 1) * 4;
    for (int kt = 0; kt < kt_end; kt++) {
        int s0 = kt * 16;
        float4 pv = *(const float4*)(probs + pbase + (long long)i_ld * TT_ + s0 + k_ld);
        float4 vv = *(const float4*)(qkv2 + vbase + (size_t)(s0 + r_ld) * 3072 + d_ld);
        __syncthreads();
        Ps[k_ld + 0][i_ld] = pv.x; Ps[k_ld + 1][i_ld] = pv.y;
        Ps[k_ld + 2][i_ld] = pv.z; Ps[k_ld + 3][i_ld] = pv.w;
        *(float4*)&Vs[r_ld][d_ld] = vv;
        __syncthreads();
        #pragma unroll
        for (int k = 0; k < 16; k++) {
            float4 a = *(const float4*)&Ps[k][ty * 4];
            float4 bv = *(const float4*)&Vs[k][tx * 4];
            float ar[4] = {a.x, a.y, a.z, a.w};
            float br[4] = {bv.x, bv.y, bv.z, bv.w};
            #pragma unroll
            for (int i = 0; i < 4; i++)
                #pragma unroll
                for (int j = 0; j < 4; j++)
                    acc[i][j] += ar[i] * br[j];
        }
    }

    size_t cbase = ((size_t)b * TT_ + (size_t)tt * 64) * DD + h * 64;
    #pragma unroll
    for (int i = 0; i < 4; i++) {
        float4 cv;
        cv.x = acc[i][0]; cv.y = acc[i][1]; cv.z = acc[i][2]; cv.w = acc[i][3];
        *(float4*)(ctx + cbase + (size_t)(ty * 4 + i) * DD + tx * 4) = cv;
    }
}

// ---------------- Launch ----------------
extern "C" void kernel_launch(void* const* d_in, const int* in_sizes, int n_in,
                              void* d_out, int out_size) {
    const float* x      = (const float*)d_in[0];
    const float* w_in   = (const float*)d_in[1];
    const float* b_in   = (const float*)d_in[2];
    const float* w_out  = (const float*)d_in[3];
    const float* b_out  = (const float*)d_in[4];
    const float* gamma  = (const float*)d_in[5];
    const float* beta   = (const float*)d_in[6];
    float* out = (float*)d_out;

    float *xn, *qkv, *qkv2, *ctx, *scores;
    cudaGetSymbolAddress((void**)&xn, g_xn);
    cudaGetSymbolAddress((void**)&qkv, g_qkv);
    cudaGetSymbolAddress((void**)&qkv2, g_qkv2);
    cudaGetSymbolAddress((void**)&ctx, g_ctx);
    cudaGetSymbolAddress((void**)&scores, g_scores);

    cudaFuncSetAttribute(tc_gemm_nt, cudaFuncAttributeMaxDynamicSharedMemorySize, GSMEM);

    bool has_attn = ((long long)out_size >= (long long)BTD + BHTT);
    float* probs = has_attn ? (out + BTD) : scores;

    // 1. pre-LN
    ln_kernel<<<ROWS, 256>>>(x, gamma, beta, xn);
    // 2. fused QKV projection (+bias): [4096,1024] @ [3072,1024]^T  (mma tf32)
    tc_gemm_nt<<<dim3(24, 32, 1), 256, GSMEM>>>(xn, 1024, 0,
                                                w_in, 1024, 0,
                                                qkv, 3072, 0,
                                                b_in, nullptr, 1024);
    // 3. RoPE on q,k (in place)
    rope_kernel<<<ROWS, 512>>>(qkv);
    // 4. second projection (bias-free), z-batched over {q,k,v}
    tc_gemm_nt<<<dim3(8, 32, 3), 256, GSMEM>>>(qkv, 3072, 1024,
                                               w_in, 1024, 1048576LL,
                                               qkv2, 3072, 1024,
                                               nullptr, nullptr, 1024);
    // 5. causal scores
    scores_kernel<<<dim3(32, 32, 32), 256>>>(qkv2, scores);
    // 6. softmax (writes probs; zero-fills masked region)
    softmax_kernel<<<BB * HH * TT_, 256>>>(scores, probs);
    // 7. ctx = P @ V
    av_kernel<<<dim3(32, 1, 32), 256>>>(probs, qkv2, ctx);
    // 8. out projection + bias + residual
    tc_gemm_nt<<<dim3(8, 32, 1), 256, GSMEM>>>(ctx, 1024, 0,
                                               w_out, 1024, 0,
                                               out, 1024, 0,
                                               b_out, x, 1024);
}

// round 7
// speedup vs baseline: 2.5206x; 1.4242x over previous
#include <cuda_runtime.h>
#include <cstdint>

// Problem constants
#define BB   2
#define TT_  2048
#define DD   1024
#define HH   16
#define ROWS (BB * TT_)               // 4096
#define BTD  (ROWS * DD)              // 4194304
#define BHTT 134217728LL              // B*H*T*T

// Scratch (allocation-free rule: __device__ globals)
__device__ float g_xn[ROWS * DD];
__device__ float g_qkv[ROWS * 3 * DD];
__device__ float g_qkv2[ROWS * 3 * DD];
__device__ float g_ctx[ROWS * DD];
__device__ float g_scores[134217728ULL];   // fallback probs if out buffer lacks attn region

__device__ __forceinline__ float warp_sum(float v) {
    #pragma unroll
    for (int o = 16; o; o >>= 1) v += __shfl_xor_sync(0xffffffffu, v, o);
    return v;
}

__device__ __forceinline__ uint32_t smem_u32(const void* p) {
    uint32_t a;
    asm("{ .reg .u64 t; cvta.to.shared.u64 t, %1; cvt.u32.u64 %0, t; }" : "=r"(a) : "l"(p));
    return a;
}
__device__ __forceinline__ uint32_t f2tf(float x) {
    uint32_t r;
    asm("cvt.rna.tf32.f32 %0, %1;" : "=r"(r) : "f"(x));
    return r;
}
__device__ __forceinline__ void mma_tf32(float* c, const uint32_t* a, const uint32_t* b) {
    asm volatile(
        "mma.sync.aligned.m16n8k8.row.col.f32.tf32.tf32.f32 "
        "{%0,%1,%2,%3}, {%4,%5,%6,%7}, {%8,%9}, {%0,%1,%2,%3};"
        : "+f"(c[0]), "+f"(c[1]), "+f"(c[2]), "+f"(c[3])
        : "r"(a[0]), "r"(a[1]), "r"(a[2]), "r"(a[3]), "r"(b[0]), "r"(b[1]));
}

// 128x64 tile mma: A[128 rows][64 k] (pre-tf32 smem, row stride asr),
// B[64 n][64 k] (row stride bsr). Warp layout 4m x 2n, warp tile 32x32.
__device__ __forceinline__ void mma_tile(const uint32_t* __restrict__ A, int asr,
                                         const uint32_t* __restrict__ B, int bsr,
                                         int wm, int wn, int r, int kg,
                                         float acc[2][4][4]) {
    #pragma unroll
    for (int mf = 0; mf < 2; mf++)
        #pragma unroll
        for (int nf = 0; nf < 4; nf++)
            #pragma unroll
            for (int i = 0; i < 4; i++) acc[mf][nf][i] = 0.f;
    const uint32_t* ab = A + (wm * 32 + r) * asr + kg;
    const uint32_t* bb = B + (wn * 32 + r) * bsr + kg;
    #pragma unroll
    for (int kst = 0; kst < 8; kst++) {
        uint32_t a[2][4], b[4][2];
        #pragma unroll
        for (int mf = 0; mf < 2; mf++) {
            const uint32_t* p = ab + mf * 16 * asr + kst * 8;
            a[mf][0] = p[0];
            a[mf][1] = p[8 * asr];
            a[mf][2] = p[4];
            a[mf][3] = p[8 * asr + 4];
        }
        #pragma unroll
        for (int nf = 0; nf < 4; nf++) {
            const uint32_t* p = bb + nf * 8 * bsr + kst * 8;
            b[nf][0] = p[0];
            b[nf][1] = p[4];
        }
        #pragma unroll
        for (int mf = 0; mf < 2; mf++)
            #pragma unroll
            for (int nf = 0; nf < 4; nf++)
                mma_tf32(acc[mf][nf], a[mf], b[nf]);
    }
}

// ======================= mma.sync tf32 NT GEMM =======================
#define PADK   36
#define STGF   (128 * PADK)
#define STAGEF (2 * STGF)
#define GSMEM  (2 * STAGEF * 4)        // 73728 bytes

__device__ __forceinline__ void load_stage(uint32_t sbase, int buf, int si,
                                           const float* __restrict__ A,
                                           const float* __restrict__ B,
                                           int lda, int ldb, int tid) {
    uint32_t as = sbase + (uint32_t)buf * (STAGEF * 4);
    uint32_t bs = as + STGF * 4;
    #pragma unroll
    for (int it = 0; it < 4; it++) {
        int idx = tid + it * 256;
        int m = idx >> 3, kq = idx & 7;
        uint32_t off = (uint32_t)(m * PADK + kq * 4) * 4;
        const float* ag = A + (size_t)m * lda + si * 32 + kq * 4;
        const float* bg = B + (size_t)m * ldb + si * 32 + kq * 4;
        asm volatile("cp.async.cg.shared.global [%0], [%1], 16;"
                     :: "r"(as + off), "l"(ag) : "memory");
        asm volatile("cp.async.cg.shared.global [%0], [%1], 16;"
                     :: "r"(bs + off), "l"(bg) : "memory");
    }
    asm volatile("cp.async.commit_group;" ::: "memory");
}

__global__ void __launch_bounds__(256, 2)
tc_gemm_nt(const float* __restrict__ A, int lda, long long sAz,
           const float* __restrict__ B, int ldb, long long sBz,
           float* __restrict__ C, int ldc, long long sCz,
           const float* __restrict__ bias, const float* __restrict__ res,
           int K) {
    extern __shared__ float smf[];
    uint32_t sb = smem_u32(smf);
    A += (long long)blockIdx.z * sAz + (size_t)blockIdx.y * 128 * lda;
    B += (long long)blockIdx.z * sBz + (size_t)blockIdx.x * 128 * ldb;
    C += (long long)blockIdx.z * sCz;
    const int m0 = blockIdx.y * 128, n0 = blockIdx.x * 128;
    const int tid = threadIdx.x;
    const int lane = tid & 31, wid = tid >> 5;
    const int wm = wid & 3, wn = wid >> 2;
    const int r = lane >> 2, kg = lane & 3;

    float acc[2][8][4];
    #pragma unroll
    for (int mf = 0; mf < 2; mf++)
        #pragma unroll
        for (int nf = 0; nf < 8; nf++)
            #pragma unroll
            for (int i = 0; i < 4; i++) acc[mf][nf][i] = 0.f;

    const int nk = K >> 5;
    load_stage(sb, 0, 0, A, B, lda, ldb, tid);

    for (int s = 0; s < nk; s++) {
        __syncthreads();
        if (s + 1 < nk) {
            load_stage(sb, (s + 1) & 1, s + 1, A, B, lda, ldb, tid);
            asm volatile("cp.async.wait_group 1;" ::: "memory");
        } else {
            asm volatile("cp.async.wait_group 0;" ::: "memory");
        }
        __syncthreads();

        const float* as = smf + (s & 1) * STAGEF;
        const float* bs = as + STGF;
        const float* abase = as + (wm * 32 + r) * PADK + kg;
        const float* bbase = bs + (wn * 64 + r) * PADK + kg;
        #pragma unroll
        for (int kst = 0; kst < 4; kst++) {
            uint32_t a[2][4], b[8][2];
            #pragma unroll
            for (int mf = 0; mf < 2; mf++) {
                const float* p = abase + mf * 16 * PADK + kst * 8;
                a[mf][0] = f2tf(p[0]);
                a[mf][1] = f2tf(p[8 * PADK]);
                a[mf][2] = f2tf(p[4]);
                a[mf][3] = f2tf(p[8 * PADK + 4]);
            }
            #pragma unroll
            for (int nf = 0; nf < 8; nf++) {
                const float* p = bbase + nf * 8 * PADK + kst * 8;
                b[nf][0] = f2tf(p[0]);
                b[nf][1] = f2tf(p[4]);
            }
            #pragma unroll
            for (int mf = 0; mf < 2; mf++)
                #pragma unroll
                for (int nf = 0; nf < 8; nf++)
                    mma_tf32(acc[mf][nf], a[mf], b[nf]);
        }
    }

    #pragma unroll
    for (int mf = 0; mf < 2; mf++) {
        int row = m0 + wm * 32 + mf * 16 + r;
        #pragma unroll
        for (int half = 0; half < 2; half++) {
            int rr = row + half * 8;
            float* crow = C + (size_t)rr * ldc;
            const float* rrow = res ? res + (size_t)rr * ldc : nullptr;
            #pragma unroll
            for (int nf = 0; nf < 8; nf++) {
                int col = n0 + wn * 64 + nf * 8 + 2 * kg;
                float2 v;
                v.x = acc[mf][nf][half * 2 + 0];
                v.y = acc[mf][nf][half * 2 + 1];
                if (bias) { v.x += bias[col]; v.y += bias[col + 1]; }
                if (rrow) {
                    const float2 rv = *(const float2*)(rrow + col);
                    v.x += rv.x; v.y += rv.y;
                }
                *(float2*)(crow + col) = v;
            }
        }
    }
}

// ---------------- LayerNorm ----------------
__global__ void ln_kernel(const float* __restrict__ x, const float* __restrict__ gamma,
                          const float* __restrict__ beta, float* __restrict__ out) {
    int row = blockIdx.x;
    int tid = threadIdx.x;
    const float4 v = ((const float4*)(x + (size_t)row * DD))[tid];
    float s  = v.x + v.y + v.z + v.w;
    float s2 = v.x * v.x + v.y * v.y + v.z * v.z + v.w * v.w;
    __shared__ float red[16];
    s = warp_sum(s); s2 = warp_sum(s2);
    if ((tid & 31) == 0) { red[tid >> 5] = s; red[(tid >> 5) + 8] = s2; }
    __syncthreads();
    float ts = 0.f, ts2 = 0.f;
    #pragma unroll
    for (int i = 0; i < 8; i++) { ts += red[i]; ts2 += red[i + 8]; }
    float mu  = ts / (float)DD;
    float var = ts2 / (float)DD - mu * mu;
    float rstd = 1.0f / sqrtf(var + 1e-5f);
    const float4 gm = ((const float4*)gamma)[tid];
    const float4 bt = ((const float4*)beta)[tid];
    float4 o;
    o.x = (v.x - mu) * rstd * gm.x + bt.x;
    o.y = (v.y - mu) * rstd * gm.y + bt.y;
    o.z = (v.z - mu) * rstd * gm.z + bt.z;
    o.w = (v.w - mu) * rstd * gm.w + bt.w;
    ((float4*)(out + (size_t)row * DD))[tid] = o;
}

// ---------------- RoPE ----------------
__global__ void rope_kernel(float* __restrict__ qkv) {
    int row = blockIdx.x;
    int t = row & (TT_ - 1);
    int h = threadIdx.x >> 5;
    int i = threadIdx.x & 31;
    float invf = expf(-logf(10000.0f) * (2.0f * (float)i) / 64.0f);
    float ang = (float)t * invf;
    float s, c;
    sincosf(ang, &s, &c);
    float* p = qkv + (size_t)row * 3072 + h * 64;
    float x1 = p[i], x2 = p[i + 32];
    p[i]      = x1 * c - x2 * s;
    p[i + 32] = x2 * c + x1 * s;
    float* pk = p + 1024;
    x1 = pk[i]; x2 = pk[i + 32];
    pk[i]      = x1 * c - x2 * s;
    pk[i + 32] = x2 * c + x1 * s;
}

// ============== fused causal scores + softmax -> probs ==============
// CTA: 128 q-rows x one bh. Pass1: online max/sum. Pass2: recompute + write.
// smem (uint/float): Qs[128][68] tf32, Ks[64][68] tf32, Ss[128][68] float,
// Red[2][128][2], RowM[128], RowI[128].
#define SMAX_SMEM ((8704 + 4352 + 8704 + 512 + 128 + 128) * 4)

__global__ void __launch_bounds__(256, 2)
smax_kernel(const float* __restrict__ qkv2, float* __restrict__ probs) {
    extern __shared__ uint32_t smu[];
    uint32_t* Qs = smu;
    uint32_t* Ks = smu + 8704;
    float*    Ss = (float*)(smu + 8704 + 4352);
    float*    Red = Ss + 8704;
    float*    RowM = Red + 512;
    float*    RowI = RowM + 128;

    const int bh = blockIdx.x, tq = blockIdx.y;
    const int b = bh >> 4, h = bh & 15;
    const int tid = threadIdx.x, lane = tid & 31, wid = tid >> 5;
    const int wm = wid & 3, wn = wid >> 2;
    const int r = lane >> 2, kg = lane & 3;
    const int jmax = 2 * tq + 2;

    // Q tile (scaled, tf32-converted)
    size_t qbase = ((size_t)(b * TT_ + tq * 128)) * 3072 + h * 64;
    #pragma unroll
    for (int it = 0; it < 8; it++) {
        int idx = tid + it * 256;
        int row = idx >> 4, c4 = (idx & 15) * 4;
        float4 v = *(const float4*)(qkv2 + qbase + (size_t)row * 3072 + c4);
        uint32_t* dst = Qs + row * 68 + c4;
        dst[0] = f2tf(v.x * 0.125f); dst[1] = f2tf(v.y * 0.125f);
        dst[2] = f2tf(v.z * 0.125f); dst[3] = f2tf(v.w * 0.125f);
    }

    int rowg[2][2];
    float m_[2][2], s_[2][2], rM[2][2], rI[2][2];
    #pragma unroll
    for (int mf = 0; mf < 2; mf++)
        #pragma unroll
        for (int hf = 0; hf < 2; hf++) {
            rowg[mf][hf] = tq * 128 + wm * 32 + mf * 16 + hf * 8 + r;
            m_[mf][hf] = -1e30f; s_[mf][hf] = 0.f;
        }

    size_t kbase = ((size_t)(b * TT_)) * 3072 + 1024 + h * 64;
    float acc[2][4][4];

    // ---------- Pass 1: stats ----------
    for (int j = 0; j < jmax; j++) {
        __syncthreads();
        #pragma unroll
        for (int it = 0; it < 4; it++) {
            int idx = tid + it * 256;
            int row = idx >> 4, c4 = (idx & 15) * 4;
            float4 v = *(const float4*)(qkv2 + kbase + (size_t)(j * 64 + row) * 3072 + c4);
            uint32_t* dst = Ks + row * 68 + c4;
            dst[0] = f2tf(v.x); dst[1] = f2tf(v.y); dst[2] = f2tf(v.z); dst[3] = f2tf(v.w);
        }
        __syncthreads();
        mma_tile(Qs, 68, Ks, 68, wm, wn, r, kg, acc);

        const bool needmask = (j >= 2 * tq);
        const int colbase = j * 64 + wn * 32;
        #pragma unroll
        for (int mf = 0; mf < 2; mf++)
            #pragma unroll
            for (int hf = 0; hf < 2; hf++) {
                float vmax = -1e30f;
                #pragma unroll
                for (int nf = 0; nf < 4; nf++)
                    #pragma unroll
                    for (int c = 0; c < 2; c++) {
                        float v = acc[mf][nf][hf * 2 + c];
                        if (needmask && (colbase + nf * 8 + 2 * kg + c) > rowg[mf][hf])
                            v = -1e30f;
                        acc[mf][nf][hf * 2 + c] = v;
                        vmax = fmaxf(vmax, v);
                    }
                if (vmax > -1e30f) {
                    float mo = m_[mf][hf];
                    float mn = fmaxf(mo, vmax);
                    float ts = 0.f;
                    #pragma unroll
                    for (int nf = 0; nf < 4; nf++)
                        #pragma unroll
                        for (int c = 0; c < 2; c++)
                            ts += __expf(acc[mf][nf][hf * 2 + c] - mn);
                    s_[mf][hf] = s_[mf][hf] * __expf(mo - mn) + ts;
                    m_[mf][hf] = mn;
                }
            }
    }

    // reduce lanes sharing a row (kg xor 1,2)
    #pragma unroll
    for (int mf = 0; mf < 2; mf++)
        #pragma unroll
        for (int hf = 0; hf < 2; hf++) {
            float m = m_[mf][hf], s = s_[mf][hf];
            #pragma unroll
            for (int o = 1; o <= 2; o <<= 1) {
                float om = __shfl_xor_sync(0xffffffffu, m, o);
                float os = __shfl_xor_sync(0xffffffffu, s, o);
                float mn = fmaxf(m, om);
                s = s * __expf(m - mn) + os * __expf(om - mn);
                m = mn;
            }
            m_[mf][hf] = m; s_[mf][hf] = s;
        }
    __syncthreads();
    if (kg == 0) {
        #pragma unroll
        for (int mf = 0; mf < 2; mf++)
            #pragma unroll
            for (int hf = 0; hf < 2; hf++) {
                int rl = wm * 32 + mf * 16 + hf * 8 + r;
                Red[(wn * 128 + rl) * 2 + 0] = m_[mf][hf];
                Red[(wn * 128 + rl) * 2 + 1] = s_[mf][hf];
            }
    }
    __syncthreads();
    if (tid < 128) {
        float m0 = Red[tid * 2], s0 = Red[tid * 2 + 1];
        float m1 = Red[(128 + tid) * 2], s1 = Red[(128 + tid) * 2 + 1];
        float mn = fmaxf(m0, m1);
        float st = s0 * __expf(m0 - mn) + s1 * __expf(m1 - mn);
        RowM[tid] = mn;
        RowI[tid] = 1.0f / st;
    }
    __syncthreads();
    #pragma unroll
    for (int mf = 0; mf < 2; mf++)
        #pragma unroll
        for (int hf = 0; hf < 2; hf++) {
            int rl = wm * 32 + mf * 16 + hf * 8 + r;
            rM[mf][hf] = RowM[rl];
            rI[mf][hf] = RowI[rl];
        }

    // ---------- Pass 2: recompute, normalize, write ----------
    for (int j = 0; j < jmax; j++) {
        __syncthreads();
        #pragma unroll
        for (int it = 0; it < 4; it++) {
            int idx = tid + it * 256;
            int row = idx >> 4, c4 = (idx & 15) * 4;
            float4 v = *(const float4*)(qkv2 + kbase + (size_t)(j * 64 + row) * 3072 + c4);
            uint32_t* dst = Ks + row * 68 + c4;
            dst[0] = f2tf(v.x); dst[1] = f2tf(v.y); dst[2] = f2tf(v.z); dst[3] = f2tf(v.w);
        }
        __syncthreads();
        mma_tile(Qs, 68, Ks, 68, wm, wn, r, kg, acc);

        const bool needmask = (j >= 2 * tq);
        const int colbase = j * 64 + wn * 32;
        #pragma unroll
        for (int mf = 0; mf < 2; mf++)
            #pragma unroll
            for (int hf = 0; hf < 2; hf++) {
                int rl = wm * 32 + mf * 16 + hf * 8 + r;
                #pragma unroll
                for (int nf = 0; nf < 4; nf++)
                    #pragma unroll
                    for (int c = 0; c < 2; c++) {
                        int coll = wn * 32 + nf * 8 + 2 * kg + c;
                        float p = 0.f;
                        if (!(needmask && (colbase + nf * 8 + 2 * kg + c) > rowg[mf][hf]))
                            p = __expf(acc[mf][nf][hf * 2 + c] - rM[mf][hf]) * rI[mf][hf];
                        Ss[rl * 68 + coll] = p;
                    }
            }
        __syncthreads();
        #pragma unroll
        for (int it = 0; it < 8; it++) {
            int idx = tid + it * 256;
            int rl = idx >> 4, c4 = (idx & 15) * 4;
            float4 v = *(const float4*)(Ss + rl * 68 + c4);
            *(float4*)(probs + ((size_t)bh * TT_ + tq * 128 + rl) * TT_ + j * 64 + c4) = v;
        }
    }

    // zero-fill cols [jmax*64, 2048)
    int zstart = jmax * 64;
    float4 z = make_float4(0.f, 0.f, 0.f, 0.f);
    for (int rl = wid; rl < 128; rl += 8) {
        float* dst = probs + ((size_t)bh * TT_ + tq * 128 + rl) * TT_;
        for (int c = zstart + lane * 4; c < TT_; c += 128)
            *(float4*)(dst + c) = z;
    }
}

// ============== ctx = P @ V (tf32 mma, causal k-range) ==============
// CTA: 128 t-rows x 64 d x one bh. Ps[128][68] tf32, Vs[64][69] tf32 (transposed).
#define AV_SMEM ((8704 + 64 * 69) * 4)

__global__ void __launch_bounds__(256)
av_mma(const float* __restrict__ probs, const float* __restrict__ qkv2,
       float* __restrict__ ctx) {
    extern __shared__ uint32_t smu[];
    uint32_t* Ps = smu;
    uint32_t* Vs = smu + 8704;

    const int bh = blockIdx.x, tq = blockIdx.y;
    const int b = bh >> 4, h = bh & 15;
    const int tid = threadIdx.x, lane = tid & 31, wid = tid >> 5;
    const int wm = wid & 3, wn = wid >> 2;
    const int r = lane >> 2, kg = lane & 3;
    const int jmax = 2 * tq + 2;

    float acc[2][4][4];
    #pragma unroll
    for (int mf = 0; mf < 2; mf++)
        #pragma unroll
        for (int nf = 0; nf < 4; nf++)
            #pragma unroll
            for (int i = 0; i < 4; i++) acc[mf][nf][i] = 0.f;

    size_t vbase = (size_t)b * TT_ * 3072 + 2048 + h * 64;

    for (int j = 0; j < jmax; j++) {
        __syncthreads();
        #pragma unroll
        for (int it = 0; it < 8; it++) {
            int idx = tid + it * 256;
            int rl = idx >> 4, c4 = (idx & 15) * 4;
            float4 v = *(const float4*)(probs + ((size_t)bh * TT_ + tq * 128 + rl) * TT_ + j * 64 + c4);
            uint32_t* dst = Ps + rl * 68 + c4;
            dst[0] = f2tf(v.x); dst[1] = f2tf(v.y); dst[2] = f2tf(v.z); dst[3] = f2tf(v.w);
        }
        #pragma unroll
        for (int it = 0; it < 4; it++) {
            int idx = tid + it * 256;
            int sl = idx >> 4, d4 = (idx & 15) * 4;
            float4 v = *(const float4*)(qkv2 + vbase + (size_t)(j * 64 + sl) * 3072 + d4);
            Vs[(d4 + 0) * 69 + sl] = f2tf(v.x);
            Vs[(d4 + 1) * 69 + sl] = f2tf(v.y);
            Vs[(d4 + 2) * 69 + sl] = f2tf(v.z);
            Vs[(d4 + 3) * 69 + sl] = f2tf(v.w);
        }
        __syncthreads();

        const uint32_t* ab = Ps + (wm * 32 + r) * 68 + kg;
        const uint32_t* bb = Vs + (wn * 32 + r) * 69 + kg;
        #pragma unroll
        for (int kst = 0; kst < 8; kst++) {
            uint32_t a[2][4], bfr[4][2];
            #pragma unroll
            for (int mf = 0; mf < 2; mf++) {
                const uint32_t* p = ab + mf * 16 * 68 + kst * 8;
                a[mf][0] = p[0]; a[mf][1] = p[8 * 68];
                a[mf][2] = p[4]; a[mf][3] = p[8 * 68 + 4];
            }
            #pragma unroll
            for (int nf = 0; nf < 4; nf++) {
                const uint32_t* p = bb + nf * 8 * 69 + kst * 8;
                bfr[nf][0] = p[0]; bfr[nf][1] = p[4];
            }
            #pragma unroll
            for (int mf = 0; mf < 2; mf++)
                #pragma unroll
                for (int nf = 0; nf < 4; nf++)
                    mma_tf32(acc[mf][nf], a[mf], bfr[nf]);
        }
    }

    #pragma unroll
    for (int mf = 0; mf < 2; mf++)
        #pragma unroll
        for (int hf = 0; hf < 2; hf++) {
            int row = b * TT_ + tq * 128 + wm * 32 + mf * 16 + hf * 8 + r;
            float* crow = ctx + (size_t)row * DD + h * 64;
            #pragma unroll
            for (int nf = 0; nf < 4; nf++) {
                int col = wn * 32 + nf * 8 + 2 * kg;
                float2 v;
                v.x = acc[mf][nf][hf * 2 + 0];
                v.y = acc[mf][nf][hf * 2 + 1];
                *(float2*)(crow + col) = v;
            }
        }
}

// ---------------- Launch ----------------
extern "C" void kernel_launch(void* const* d_in, const int* in_sizes, int n_in,
                              void* d_out, int out_size) {
    const float* x      = (const float*)d_in[0];
    const float* w_in   = (const float*)d_in[1];
    const float* b_in   = (const float*)d_in[2];
    const float* w_out  = (const float*)d_in[3];
    const float* b_out  = (const float*)d_in[4];
    const float* gamma  = (const float*)d_in[5];
    const float* beta   = (const float*)d_in[6];
    float* out = (float*)d_out;

    float *xn, *qkv, *qkv2, *ctx, *scores;
    cudaGetSymbolAddress((void**)&xn, g_xn);
    cudaGetSymbolAddress((void**)&qkv, g_qkv);
    cudaGetSymbolAddress((void**)&qkv2, g_qkv2);
    cudaGetSymbolAddress((void**)&ctx, g_ctx);
    cudaGetSymbolAddress((void**)&scores, g_scores);

    cudaFuncSetAttribute(tc_gemm_nt, cudaFuncAttributeMaxDynamicSharedMemorySize, GSMEM);
    cudaFuncSetAttribute(smax_kernel, cudaFuncAttributeMaxDynamicSharedMemorySize, SMAX_SMEM);
    cudaFuncSetAttribute(av_mma, cudaFuncAttributeMaxDynamicSharedMemorySize, AV_SMEM);

    bool has_attn = ((long long)out_size >= (long long)BTD + BHTT);
    float* probs = has_attn ? (out + BTD) : scores;

    // 1. pre-LN
    ln_kernel<<<ROWS, 256>>>(x, gamma, beta, xn);
    // 2. fused QKV projection (+bias)
    tc_gemm_nt<<<dim3(24, 32, 1), 256, GSMEM>>>(xn, 1024, 0,
                                                w_in, 1024, 0,
                                                qkv, 3072, 0,
                                                b_in, nullptr, 1024);
    // 3. RoPE on q,k (in place)
    rope_kernel<<<ROWS, 512>>>(qkv);
    // 4. second projection (bias-free), z-batched over {q,k,v}
    tc_gemm_nt<<<dim3(8, 32, 3), 256, GSMEM>>>(qkv, 3072, 1024,
                                               w_in, 1024, 1048576LL,
                                               qkv2, 3072, 1024,
                                               nullptr, nullptr, 1024);
    // 5+6. fused causal scores + softmax -> probs
    smax_kernel<<<dim3(32, 16), 256, SMAX_SMEM>>>(qkv2, probs);
    // 7. ctx = P @ V (tf32 mma)
    av_mma<<<dim3(32, 16), 256, AV_SMEM>>>(probs, qkv2, ctx);
    // 8. out projection + bias + residual
    tc_gemm_nt<<<dim3(8, 32, 1), 256, GSMEM>>>(ctx, 1024, 0,
                                               w_out, 1024, 0,
                                               out, 1024, 0,
                                               b_out, x, 1024);
}

// round 8
// speedup vs baseline: 2.9148x; 1.1564x over previous
#include <cuda_runtime.h>
#include <cstdint>

// Problem constants
#define BB   2
#define TT_  2048
#define DD   1024
#define HH   16
#define ROWS (BB * TT_)               // 4096
#define BTD  (ROWS * DD)              // 4194304
#define BHTT 134217728LL              // B*H*T*T

// Scratch (allocation-free rule: __device__ globals)
__device__ float g_xn[ROWS * DD];
__device__ float g_qkv[ROWS * 3 * DD];
__device__ float g_qkv2[ROWS * 3 * DD];
__device__ float g_ctx[ROWS * DD];
__device__ float g_wr_in[3 * DD * DD];
__device__ float g_wr_out[DD * DD];
__device__ float g_scores[134217728ULL];   // fallback probs

__device__ __forceinline__ float warp_sum(float v) {
    #pragma unroll
    for (int o = 16; o; o >>= 1) v += __shfl_xor_sync(0xffffffffu, v, o);
    return v;
}
__device__ __forceinline__ uint32_t smem_u32(const void* p) {
    uint32_t a;
    asm("{ .reg .u64 t; cvta.to.shared.u64 t, %1; cvt.u32.u64 %0, t; }" : "=r"(a) : "l"(p));
    return a;
}
__device__ __forceinline__ uint32_t f2tf(float x) {
    uint32_t r;
    asm("cvt.rna.tf32.f32 %0, %1;" : "=r"(r) : "f"(x));
    return r;
}
__device__ __forceinline__ float rndtf(float x) { return __uint_as_float(f2tf(x)); }

__device__ __forceinline__ void mma_tf32(float* c, const uint32_t* a, const uint32_t* b) {
    asm volatile(
        "mma.sync.aligned.m16n8k8.row.col.f32.tf32.tf32.f32 "
        "{%0,%1,%2,%3}, {%4,%5,%6,%7}, {%8,%9}, {%0,%1,%2,%3};"
        : "+f"(c[0]), "+f"(c[1]), "+f"(c[2]), "+f"(c[3])
        : "r"(a[0]), "r"(a[1]), "r"(a[2]), "r"(a[3]), "r"(b[0]), "r"(b[1]));
}

#define CPA16(dst, src) \
    asm volatile("cp.async.cg.shared.global [%0], [%1], 16;" :: "r"(dst), "l"(src) : "memory")
#define CPCOMMIT() asm volatile("cp.async.commit_group;" ::: "memory")

// 128x64 tile mma (raw tf32-pattern smem). Warp layout 4m x 2n, warp tile 32x32.
__device__ __forceinline__ void mma_tile(const uint32_t* __restrict__ A, int asr,
                                         const uint32_t* __restrict__ B, int bsr,
                                         int wm, int wn, int r, int kg,
                                         float acc[2][4][4]) {
    #pragma unroll
    for (int mf = 0; mf < 2; mf++)
        #pragma unroll
        for (int nf = 0; nf < 4; nf++)
            #pragma unroll
            for (int i = 0; i < 4; i++) acc[mf][nf][i] = 0.f;
    const uint32_t* ab = A + (wm * 32 + r) * asr + kg;
    const uint32_t* bb = B + (wn * 32 + r) * bsr + kg;
    #pragma unroll
    for (int kst = 0; kst < 8; kst++) {
        uint32_t a[2][4], b[4][2];
        #pragma unroll
        for (int mf = 0; mf < 2; mf++) {
            const uint32_t* p = ab + mf * 16 * asr + kst * 8;
            a[mf][0] = p[0]; a[mf][1] = p[8 * asr];
            a[mf][2] = p[4]; a[mf][3] = p[8 * asr + 4];
        }
        #pragma unroll
        for (int nf = 0; nf < 4; nf++) {
            const uint32_t* p = bb + nf * 8 * bsr + kst * 8;
            b[nf][0] = p[0]; b[nf][1] = p[4];
        }
        #pragma unroll
        for (int mf = 0; mf < 2; mf++)
            #pragma unroll
            for (int nf = 0; nf < 4; nf++)
                mma_tf32(acc[mf][nf], a[mf], b[nf]);
    }
}

// ---------------- tf32 rounding kernel (weights) ----------------
__global__ void round_kernel(const float* __restrict__ in, float* __restrict__ out, int n4) {
    for (int i = blockIdx.x * blockDim.x + threadIdx.x; i < n4; i += gridDim.x * blockDim.x) {
        float4 v = ((const float4*)in)[i];
        v.x = rndtf(v.x); v.y = rndtf(v.y); v.z = rndtf(v.z); v.w = rndtf(v.w);
        ((float4*)out)[i] = v;
    }
}

// ======================= mma.sync tf32 NT GEMM =======================
// Inputs pre-rounded to tf32 bit patterns; no cvt in mainloop.
#define PADK   36
#define STGF   (128 * PADK)
#define STAGEF (2 * STGF)
#define GSMEM  (2 * STAGEF * 4)

__device__ __forceinline__ void load_stage(uint32_t sbase, int buf, int si,
                                           const float* __restrict__ A,
                                           const float* __restrict__ B,
                                           int lda, int ldb, int tid) {
    uint32_t as = sbase + (uint32_t)buf * (STAGEF * 4);
    uint32_t bs = as + STGF * 4;
    #pragma unroll
    for (int it = 0; it < 4; it++) {
        int idx = tid + it * 256;
        int m = idx >> 3, kq = idx & 7;
        uint32_t off = (uint32_t)(m * PADK + kq * 4) * 4;
        CPA16(as + off, A + (size_t)m * lda + si * 32 + kq * 4);
        CPA16(bs + off, B + (size_t)m * ldb + si * 32 + kq * 4);
    }
    CPCOMMIT();
}

__global__ void __launch_bounds__(256, 2)
tc_gemm_nt(const float* __restrict__ A, int lda, long long sAz,
           const float* __restrict__ B, int ldb, long long sBz,
           float* __restrict__ C, int ldc, long long sCz,
           const float* __restrict__ bias, const float* __restrict__ res,
           int K, int round_c) {
    extern __shared__ float smf[];
    uint32_t sb = smem_u32(smf);
    A += (long long)blockIdx.z * sAz + (size_t)blockIdx.y * 128 * lda;
    B += (long long)blockIdx.z * sBz + (size_t)blockIdx.x * 128 * ldb;
    C += (long long)blockIdx.z * sCz;
    const int m0 = blockIdx.y * 128, n0 = blockIdx.x * 128;
    const int tid = threadIdx.x;
    const int lane = tid & 31, wid = tid >> 5;
    const int wm = wid & 3, wn = wid >> 2;
    const int r = lane >> 2, kg = lane & 3;

    float acc[2][8][4];
    #pragma unroll
    for (int mf = 0; mf < 2; mf++)
        #pragma unroll
        for (int nf = 0; nf < 8; nf++)
            #pragma unroll
            for (int i = 0; i < 4; i++) acc[mf][nf][i] = 0.f;

    const int nk = K >> 5;
    load_stage(sb, 0, 0, A, B, lda, ldb, tid);

    for (int s = 0; s < nk; s++) {
        __syncthreads();
        if (s + 1 < nk) {
            load_stage(sb, (s + 1) & 1, s + 1, A, B, lda, ldb, tid);
            asm volatile("cp.async.wait_group 1;" ::: "memory");
        } else {
            asm volatile("cp.async.wait_group 0;" ::: "memory");
        }
        __syncthreads();

        const uint32_t* as = (const uint32_t*)smf + (s & 1) * STAGEF;
        const uint32_t* bs = as + STGF;
        const uint32_t* abase = as + (wm * 32 + r) * PADK + kg;
        const uint32_t* bbase = bs + (wn * 64 + r) * PADK + kg;
        #pragma unroll
        for (int kst = 0; kst < 4; kst++) {
            uint32_t a[2][4], b[8][2];
            #pragma unroll
            for (int mf = 0; mf < 2; mf++) {
                const uint32_t* p = abase + mf * 16 * PADK + kst * 8;
                a[mf][0] = p[0]; a[mf][1] = p[8 * PADK];
                a[mf][2] = p[4]; a[mf][3] = p[8 * PADK + 4];
            }
            #pragma unroll
            for (int nf = 0; nf < 8; nf++) {
                const uint32_t* p = bbase + nf * 8 * PADK + kst * 8;
                b[nf][0] = p[0]; b[nf][1] = p[4];
            }
            #pragma unroll
            for (int mf = 0; mf < 2; mf++)
                #pragma unroll
                for (int nf = 0; nf < 8; nf++)
                    mma_tf32(acc[mf][nf], a[mf], b[nf]);
        }
    }

    #pragma unroll
    for (int mf = 0; mf < 2; mf++) {
        int row = m0 + wm * 32 + mf * 16 + r;
        #pragma unroll
        for (int half = 0; half < 2; half++) {
            int rr = row + half * 8;
            float* crow = C + (size_t)rr * ldc;
            const float* rrow = res ? res + (size_t)rr * ldc : nullptr;
            #pragma unroll
            for (int nf = 0; nf < 8; nf++) {
                int col = n0 + wn * 64 + nf * 8 + 2 * kg;
                float2 v;
                v.x = acc[mf][nf][half * 2 + 0];
                v.y = acc[mf][nf][half * 2 + 1];
                if (bias) { v.x += bias[col]; v.y += bias[col + 1]; }
                if (rrow) {
                    const float2 rv = *(const float2*)(rrow + col);
                    v.x += rv.x; v.y += rv.y;
                }
                if (round_c) { v.x = rndtf(v.x); v.y = rndtf(v.y); }
                *(float2*)(crow + col) = v;
            }
        }
    }
}

// ---------------- LayerNorm (writes tf32-rounded) ----------------
__global__ void ln_kernel(const float* __restrict__ x, const float* __restrict__ gamma,
                          const float* __restrict__ beta, float* __restrict__ out) {
    int row = blockIdx.x;
    int tid = threadIdx.x;
    const float4 v = ((const float4*)(x + (size_t)row * DD))[tid];
    float s  = v.x + v.y + v.z + v.w;
    float s2 = v.x * v.x + v.y * v.y + v.z * v.z + v.w * v.w;
    __shared__ float red[16];
    s = warp_sum(s); s2 = warp_sum(s2);
    if ((tid & 31) == 0) { red[tid >> 5] = s; red[(tid >> 5) + 8] = s2; }
    __syncthreads();
    float ts = 0.f, ts2 = 0.f;
    #pragma unroll
    for (int i = 0; i < 8; i++) { ts += red[i]; ts2 += red[i + 8]; }
    float mu  = ts / (float)DD;
    float var = ts2 / (float)DD - mu * mu;
    float rstd = 1.0f / sqrtf(var + 1e-5f);
    const float4 gm = ((const float4*)gamma)[tid];
    const float4 bt = ((const float4*)beta)[tid];
    float4 o;
    o.x = rndtf((v.x - mu) * rstd * gm.x + bt.x);
    o.y = rndtf((v.y - mu) * rstd * gm.y + bt.y);
    o.z = rndtf((v.z - mu) * rstd * gm.z + bt.z);
    o.w = rndtf((v.w - mu) * rstd * gm.w + bt.w);
    ((float4*)(out + (size_t)row * DD))[tid] = o;
}

// ---------------- RoPE (writes tf32-rounded) ----------------
__global__ void rope_kernel(float* __restrict__ qkv) {
    int row = blockIdx.x;
    int t = row & (TT_ - 1);
    int h = threadIdx.x >> 5;
    int i = threadIdx.x & 31;
    float invf = expf(-logf(10000.0f) * (2.0f * (float)i) / 64.0f);
    float ang = (float)t * invf;
    float s, c;
    sincosf(ang, &s, &c);
    float* p = qkv + (size_t)row * 3072 + h * 64;
    float x1 = p[i], x2 = p[i + 32];
    p[i]      = rndtf(x1 * c - x2 * s);
    p[i + 32] = rndtf(x2 * c + x1 * s);
    float* pk = p + 1024;
    x1 = pk[i]; x2 = pk[i + 32];
    pk[i]      = rndtf(x1 * c - x2 * s);
    pk[i + 32] = rndtf(x2 * c + x1 * s);
}

// ============== fused causal scores + softmax -> probs ==============
// smem: Qs[128][68], Ks[2][64][68], Ss[128][68], Red[512], RowM[128], RowI[128]
#define SMAX_SMEM ((8704 + 8704 + 8704 + 512 + 128 + 128) * 4)

__device__ __forceinline__ void smax_loadK(uint32_t kdst, const float* __restrict__ kptr, int tid) {
    #pragma unroll
    for (int it = 0; it < 4; it++) {
        int idx = tid + it * 256;
        int row = idx >> 4, c4 = (idx & 15) * 4;
        CPA16(kdst + (uint32_t)(row * 68 + c4) * 4, kptr + (size_t)row * 3072 + c4);
    }
}

__global__ void __launch_bounds__(256, 2)
smax_kernel(const float* __restrict__ qkv2, float* __restrict__ probs) {
    extern __shared__ uint32_t smu[];
    uint32_t* Qs = smu;
    uint32_t* Ks = smu + 8704;            // 2 buffers of 4352
    float*    Ss = (float*)(smu + 17408);
    float*    Red = Ss + 8704;
    float*    RowM = Red + 512;
    float*    RowI = RowM + 128;
    uint32_t sb = smem_u32(smu);
    const uint32_t KsB = sb + 8704 * 4;

    const int bh = blockIdx.x, tq = blockIdx.y;
    const int b = bh >> 4, h = bh & 15;
    const int tid = threadIdx.x, lane = tid & 31, wid = tid >> 5;
    const int wm = wid & 3, wn = wid >> 2;
    const int r = lane >> 2, kg = lane & 3;
    const int jmax = 2 * tq + 2;

    const float* qptr = qkv2 + ((size_t)(b * TT_ + tq * 128)) * 3072 + h * 64;
    const float* kbase = qkv2 + ((size_t)(b * TT_)) * 3072 + 1024 + h * 64;

    // prologue pass1: Q + K0 in one group
    #pragma unroll
    for (int it = 0; it < 8; it++) {
        int idx = tid + it * 256;
        int row = idx >> 4, c4 = (idx & 15) * 4;
        CPA16(sb + (uint32_t)(row * 68 + c4) * 4, qptr + (size_t)row * 3072 + c4);
    }
    smax_loadK(KsB, kbase, tid);
    CPCOMMIT();

    int rowg[2][2];
    float m_[2][2], s_[2][2], rM[2][2], rI[2][2];
    #pragma unroll
    for (int mf = 0; mf < 2; mf++)
        #pragma unroll
        for (int hf = 0; hf < 2; hf++) {
            rowg[mf][hf] = tq * 128 + wm * 32 + mf * 16 + hf * 8 + r;
            m_[mf][hf] = -1e30f; s_[mf][hf] = 0.f;
        }

    float acc[2][4][4];

    // ---------- Pass 1 ----------
    for (int j = 0; j < jmax; j++) {
        if (j + 1 < jmax) {
            smax_loadK(KsB + ((j + 1) & 1) * 4352 * 4, kbase + (size_t)(j + 1) * 64 * 3072, tid);
            CPCOMMIT();
            asm volatile("cp.async.wait_group 1;" ::: "memory");
        } else {
            asm volatile("cp.async.wait_group 0;" ::: "memory");
        }
        __syncthreads();
        mma_tile(Qs, 68, Ks + (j & 1) * 4352, 68, wm, wn, r, kg, acc);

        const bool needmask = (j >= 2 * tq);
        const int colbase = j * 64 + wn * 32;
        #pragma unroll
        for (int mf = 0; mf < 2; mf++)
            #pragma unroll
            for (int hf = 0; hf < 2; hf++) {
                float vmax = -1e30f;
                #pragma unroll
                for (int nf = 0; nf < 4; nf++)
                    #pragma unroll
                    for (int c = 0; c < 2; c++) {
                        float v = acc[mf][nf][hf * 2 + c] * 0.125f;
                        if (needmask && (colbase + nf * 8 + 2 * kg + c) > rowg[mf][hf])
                            v = -1e30f;
                        acc[mf][nf][hf * 2 + c] = v;
                        vmax = fmaxf(vmax, v);
                    }
                if (vmax > -1e30f) {
                    float mo = m_[mf][hf];
                    float mn = fmaxf(mo, vmax);
                    float ts = 0.f;
                    #pragma unroll
                    for (int nf = 0; nf < 4; nf++)
                        #pragma unroll
                        for (int c = 0; c < 2; c++)
                            ts += __expf(acc[mf][nf][hf * 2 + c] - mn);
                    s_[mf][hf] = s_[mf][hf] * __expf(mo - mn) + ts;
                    m_[mf][hf] = mn;
                }
            }
        __syncthreads();
    }

    // reduce lanes sharing a row
    #pragma unroll
    for (int mf = 0; mf < 2; mf++)
        #pragma unroll
        for (int hf = 0; hf < 2; hf++) {
            float m = m_[mf][hf], s = s_[mf][hf];
            #pragma unroll
            for (int o = 1; o <= 2; o <<= 1) {
                float om = __shfl_xor_sync(0xffffffffu, m, o);
                float os = __shfl_xor_sync(0xffffffffu, s, o);
                float mn = fmaxf(m, om);
                s = s * __expf(m - mn) + os * __expf(om - mn);
                m = mn;
            }
            m_[mf][hf] = m; s_[mf][hf] = s;
        }
    if (kg == 0) {
        #pragma unroll
        for (int mf = 0; mf < 2; mf++)
            #pragma unroll
            for (int hf = 0; hf < 2; hf++) {
                int rl = wm * 32 + mf * 16 + hf * 8 + r;
                Red[(wn * 128 + rl) * 2 + 0] = m_[mf][hf];
                Red[(wn * 128 + rl) * 2 + 1] = s_[mf][hf];
            }
    }
    __syncthreads();
    if (tid < 128) {
        float m0 = Red[tid * 2], s0 = Red[tid * 2 + 1];
        float m1 = Red[(128 + tid) * 2], s1 = Red[(128 + tid) * 2 + 1];
        float mn = fmaxf(m0, m1);
        float st = s0 * __expf(m0 - mn) + s1 * __expf(m1 - mn);
        RowM[tid] = mn;
        RowI[tid] = 1.0f / st;
    }
    __syncthreads();
    #pragma unroll
    for (int mf = 0; mf < 2; mf++)
        #pragma unroll
        for (int hf = 0; hf < 2; hf++) {
            int rl = wm * 32 + mf * 16 + hf * 8 + r;
            rM[mf][hf] = RowM[rl];
            rI[mf][hf] = RowI[rl];
        }
    __syncthreads();

    // ---------- Pass 2 ----------
    smax_loadK(KsB, kbase, tid);
    CPCOMMIT();
    for (int j = 0; j < jmax; j++) {
        if (j + 1 < jmax) {
            smax_loadK(KsB + ((j + 1) & 1) * 4352 * 4, kbase + (size_t)(j + 1) * 64 * 3072, tid);
            CPCOMMIT();
            asm volatile("cp.async.wait_group 1;" ::: "memory");
        } else {
            asm volatile("cp.async.wait_group 0;" ::: "memory");
        }
        __syncthreads();
        mma_tile(Qs, 68, Ks + (j & 1) * 4352, 68, wm, wn, r, kg, acc);

        const bool needmask = (j >= 2 * tq);
        const int colbase = j * 64 + wn * 32;
        #pragma unroll
        for (int mf = 0; mf < 2; mf++)
            #pragma unroll
            for (int hf = 0; hf < 2; hf++) {
                int rl = wm * 32 + mf * 16 + hf * 8 + r;
                #pragma unroll
                for (int nf = 0; nf < 4; nf++)
                    #pragma unroll
                    for (int c = 0; c < 2; c++) {
                        int coll = wn * 32 + nf * 8 + 2 * kg + c;
                        float p = 0.f;
                        if (!(needmask && (colbase + nf * 8 + 2 * kg + c) > rowg[mf][hf]))
                            p = __expf(acc[mf][nf][hf * 2 + c] * 0.125f - rM[mf][hf]) * rI[mf][hf];
                        Ss[rl * 68 + coll] = p;
                    }
            }
        __syncthreads();
        #pragma unroll
        for (int it = 0; it < 8; it++) {
            int idx = tid + it * 256;
            int rl = idx >> 4, c4 = (idx & 15) * 4;
            float4 v = *(const float4*)(Ss + rl * 68 + c4);
            *(float4*)(probs + ((size_t)bh * TT_ + tq * 128 + rl) * TT_ + j * 64 + c4) = v;
        }
    }

    // zero-fill cols [jmax*64, 2048)
    int zstart = jmax * 64;
    float4 z = make_float4(0.f, 0.f, 0.f, 0.f);
    for (int rl = wid; rl < 128; rl += 8) {
        float* dst = probs + ((size_t)bh * TT_ + tq * 128 + rl) * TT_;
        for (int c = zstart + lane * 4; c < TT_; c += 128)
            *(float4*)(dst + c) = z;
    }
}

// ============== ctx = P @ V (tf32 mma, pipelined) ==============
// smem: Ps[2][128][68] raw fp32, Vs[2][64][69] tf32-pattern (transposed)
#define AV_SMEM ((17408 + 8832) * 4)

__global__ void __launch_bounds__(256, 2)
av_mma(const float* __restrict__ probs, const float* __restrict__ qkv2,
       float* __restrict__ ctx) {
    extern __shared__ uint32_t smu[];
    uint32_t* Ps = smu;                   // 2 x 8704
    uint32_t* Vs = smu + 17408;           // 2 x 4416
    uint32_t sb = smem_u32(smu);

    const int bh = blockIdx.x, tq = blockIdx.y;
    const int b = bh >> 4, h = bh & 15;
    const int tid = threadIdx.x, lane = tid & 31, wid = tid >> 5;
    const int wm = wid & 3, wn = wid >> 2;
    const int r = lane >> 2, kg = lane & 3;
    const int jmax = 2 * tq + 2;

    float acc[2][4][4];
    #pragma unroll
    for (int mf = 0; mf < 2; mf++)
        #pragma unroll
        for (int nf = 0; nf < 4; nf++)
            #pragma unroll
            for (int i = 0; i < 4; i++) acc[mf][nf][i] = 0.f;

    const float* pbase = probs + ((size_t)bh * TT_ + tq * 128) * TT_;
    const float* vbase = qkv2 + (size_t)b * TT_ * 3072 + 2048 + h * 64;

    // V chunk geometry: idx -> (sl, d4)
    int vsl[4], vd4[4];
    #pragma unroll
    for (int it = 0; it < 4; it++) {
        int idx = tid + it * 256;
        vsl[it] = idx >> 4;
        vd4[it] = (idx & 15) * 4;
    }

    // prologue: P0 async, V0 regs
    #pragma unroll
    for (int it = 0; it < 8; it++) {
        int idx = tid + it * 256;
        int rl = idx >> 4, c4 = (idx & 15) * 4;
        CPA16(sb + (uint32_t)(rl * 68 + c4) * 4, pbase + (size_t)rl * TT_ + c4);
    }
    CPCOMMIT();
    float4 vr[4];
    #pragma unroll
    for (int it = 0; it < 4; it++)
        vr[it] = *(const float4*)(vbase + (size_t)vsl[it] * 3072 + vd4[it]);

    for (int j = 0; j < jmax; j++) {
        float4 vr2[4];
        if (j + 1 < jmax) {
            #pragma unroll
            for (int it = 0; it < 8; it++) {
                int idx = tid + it * 256;
                int rl = idx >> 4, c4 = (idx & 15) * 4;
                CPA16(sb + (uint32_t)(((j + 1) & 1) * 8704 + rl * 68 + c4) * 4,
                      pbase + (size_t)rl * TT_ + (j + 1) * 64 + c4);
            }
            CPCOMMIT();
            #pragma unroll
            for (int it = 0; it < 4; it++)
                vr2[it] = *(const float4*)(vbase + (size_t)((j + 1) * 64 + vsl[it]) * 3072 + vd4[it]);
        }
        // store V(j) transposed
        uint32_t* vbuf = Vs + (j & 1) * 4416;
        #pragma unroll
        for (int it = 0; it < 4; it++) {
            vbuf[(vd4[it] + 0) * 69 + vsl[it]] = __float_as_uint(vr[it].x);
            vbuf[(vd4[it] + 1) * 69 + vsl[it]] = __float_as_uint(vr[it].y);
            vbuf[(vd4[it] + 2) * 69 + vsl[it]] = __float_as_uint(vr[it].z);
            vbuf[(vd4[it] + 3) * 69 + vsl[it]] = __float_as_uint(vr[it].w);
        }
        if (j + 1 < jmax) {
            asm volatile("cp.async.wait_group 1;" ::: "memory");
        } else {
            asm volatile("cp.async.wait_group 0;" ::: "memory");
        }
        __syncthreads();

        const float* pf = (const float*)(Ps + (j & 1) * 8704);
        const uint32_t* bb = vbuf + (wn * 32 + r) * 69 + kg;
        const float* ab = pf + (wm * 32 + r) * 68 + kg;
        #pragma unroll
        for (int kst = 0; kst < 8; kst++) {
            uint32_t a[2][4], bfr[4][2];
            #pragma unroll
            for (int mf = 0; mf < 2; mf++) {
                const float* p = ab + mf * 16 * 68 + kst * 8;
                a[mf][0] = f2tf(p[0]); a[mf][1] = f2tf(p[8 * 68]);
                a[mf][2] = f2tf(p[4]); a[mf][3] = f2tf(p[8 * 68 + 4]);
            }
            #pragma unroll
            for (int nf = 0; nf < 4; nf++) {
                const uint32_t* p = bb + nf * 8 * 69 + kst * 8;
                bfr[nf][0] = p[0]; bfr[nf][1] = p[4];
            }
            #pragma unroll
            for (int mf = 0; mf < 2; mf++)
                #pragma unroll
                for (int nf = 0; nf < 4; nf++)
                    mma_tf32(acc[mf][nf], a[mf], bfr[nf]);
        }
        #pragma unroll
        for (int it = 0; it < 4; it++) vr[it] = vr2[it];
        __syncthreads();
    }

    #pragma unroll
    for (int mf = 0; mf < 2; mf++)
        #pragma unroll
        for (int hf = 0; hf < 2; hf++) {
            int row = b * TT_ + tq * 128 + wm * 32 + mf * 16 + hf * 8 + r;
            float* crow = ctx + (size_t)row * DD + h * 64;
            #pragma unroll
            for (int nf = 0; nf < 4; nf++) {
                int col = wn * 32 + nf * 8 + 2 * kg;
                float2 v;
                v.x = rndtf(acc[mf][nf][hf * 2 + 0]);
                v.y = rndtf(acc[mf][nf][hf * 2 + 1]);
                *(float2*)(crow + col) = v;
            }
        }
}

// ---------------- Launch ----------------
extern "C" void kernel_launch(void* const* d_in, const int* in_sizes, int n_in,
                              void* d_out, int out_size) {
    const float* x      = (const float*)d_in[0];
    const float* w_in   = (const float*)d_in[1];
    const float* b_in   = (const float*)d_in[2];
    const float* w_out  = (const float*)d_in[3];
    const float* b_out  = (const float*)d_in[4];
    const float* gamma  = (const float*)d_in[5];
    const float* beta   = (const float*)d_in[6];
    float* out = (float*)d_out;

    float *xn, *qkv, *qkv2, *ctx, *scores, *wr_in, *wr_out;
    cudaGetSymbolAddress((void**)&xn, g_xn);
    cudaGetSymbolAddress((void**)&qkv, g_qkv);
    cudaGetSymbolAddress((void**)&qkv2, g_qkv2);
    cudaGetSymbolAddress((void**)&ctx, g_ctx);
    cudaGetSymbolAddress((void**)&scores, g_scores);
    cudaGetSymbolAddress((void**)&wr_in, g_wr_in);
    cudaGetSymbolAddress((void**)&wr_out, g_wr_out);

    cudaFuncSetAttribute(tc_gemm_nt, cudaFuncAttributeMaxDynamicSharedMemorySize, GSMEM);
    cudaFuncSetAttribute(smax_kernel, cudaFuncAttributeMaxDynamicSharedMemorySize, SMAX_SMEM);
    cudaFuncSetAttribute(av_mma, cudaFuncAttributeMaxDynamicSharedMemorySize, AV_SMEM);

    bool has_attn = ((long long)out_size >= (long long)BTD + BHTT);
    float* probs = has_attn ? (out + BTD) : scores;

    // 0. round weights to tf32 patterns
    round_kernel<<<1024, 256>>>(w_in, wr_in, 3 * DD * DD / 4);
    round_kernel<<<512, 256>>>(w_out, wr_out, DD * DD / 4);
    // 1. pre-LN (tf32-rounded output)
    ln_kernel<<<ROWS, 256>>>(x, gamma, beta, xn);
    // 2. fused QKV projection (+bias), rounded output
    tc_gemm_nt<<<dim3(24, 32, 1), 256, GSMEM>>>(xn, 1024, 0,
                                                wr_in, 1024, 0,
                                                qkv, 3072, 0,
                                                b_in, nullptr, 1024, 1);
    // 3. RoPE on q,k (in place, rounded)
    rope_kernel<<<ROWS, 512>>>(qkv);
    // 4. second projection, z-batched, rounded output
    tc_gemm_nt<<<dim3(8, 32, 3), 256, GSMEM>>>(qkv, 3072, 1024,
                                               wr_in, 1024, 1048576LL,
                                               qkv2, 3072, 1024,
                                               nullptr, nullptr, 1024, 1);
    // 5+6. fused causal scores + softmax -> probs
    smax_kernel<<<dim3(32, 16), 256, SMAX_SMEM>>>(qkv2, probs);
    // 7. ctx = P @ V
    av_mma<<<dim3(32, 16), 256, AV_SMEM>>>(probs, qkv2, ctx);
    // 8. out projection + bias + residual (fp32 output)
    tc_gemm_nt<<<dim3(8, 32, 1), 256, GSMEM>>>(ctx, 1024, 0,
                                               wr_out, 1024, 0,
                                               out, 1024, 0,
                                               b_out, x, 1024, 0);
}

// round 9
// speedup vs baseline: 2.9650x; 1.0172x over previous
#include <cuda_runtime.h>
#include <cstdint>

// Problem constants
#define BB   2
#define TT_  2048
#define DD   1024
#define HH   16
#define ROWS (BB * TT_)               // 4096
#define BTD  (ROWS * DD)              // 4194304
#define BHTT 134217728LL              // B*H*T*T

// Scratch (allocation-free rule: __device__ globals)
__device__ float g_xn[ROWS * DD];
__device__ float g_qkv[ROWS * 3 * DD];
__device__ float g_qkv2[ROWS * 3 * DD];
__device__ float g_ctx[ROWS * DD];
__device__ float g_wr_in[3 * DD * DD];
__device__ float g_wr_out[DD * DD];
__device__ float g_scores[134217728ULL];   // fallback probs

__device__ __forceinline__ float warp_sum(float v) {
    #pragma unroll
    for (int o = 16; o; o >>= 1) v += __shfl_xor_sync(0xffffffffu, v, o);
    return v;
}
__device__ __forceinline__ uint32_t smem_u32(const void* p) {
    uint32_t a;
    asm("{ .reg .u64 t; cvta.to.shared.u64 t, %1; cvt.u32.u64 %0, t; }" : "=r"(a) : "l"(p));
    return a;
}
__device__ __forceinline__ uint32_t f2tf(float x) {
    uint32_t r;
    asm("cvt.rna.tf32.f32 %0, %1;" : "=r"(r) : "f"(x));
    return r;
}
__device__ __forceinline__ float rndtf(float x) { return __uint_as_float(f2tf(x)); }

__device__ __forceinline__ void mma_tf32(float* c, const uint32_t* a, const uint32_t* b) {
    asm volatile(
        "mma.sync.aligned.m16n8k8.row.col.f32.tf32.tf32.f32 "
        "{%0,%1,%2,%3}, {%4,%5,%6,%7}, {%8,%9}, {%0,%1,%2,%3};"
        : "+f"(c[0]), "+f"(c[1]), "+f"(c[2]), "+f"(c[3])
        : "r"(a[0]), "r"(a[1]), "r"(a[2]), "r"(a[3]), "r"(b[0]), "r"(b[1]));
}

#define CPA16(dst, src) \
    asm volatile("cp.async.cg.shared.global [%0], [%1], 16;" :: "r"(dst), "l"(src) : "memory")
#define CPCOMMIT() asm volatile("cp.async.commit_group;" ::: "memory")

// 128x64 tile mma (raw tf32-pattern smem). Warp layout 4m x 2n, warp tile 32x32.
__device__ __forceinline__ void mma_tile(const uint32_t* __restrict__ A, int asr,
                                         const uint32_t* __restrict__ B, int bsr,
                                         int wm, int wn, int r, int kg,
                                         float acc[2][4][4]) {
    #pragma unroll
    for (int mf = 0; mf < 2; mf++)
        #pragma unroll
        for (int nf = 0; nf < 4; nf++)
            #pragma unroll
            for (int i = 0; i < 4; i++) acc[mf][nf][i] = 0.f;
    const uint32_t* ab = A + (wm * 32 + r) * asr + kg;
    const uint32_t* bb = B + (wn * 32 + r) * bsr + kg;
    #pragma unroll
    for (int kst = 0; kst < 8; kst++) {
        uint32_t a[2][4], b[4][2];
        #pragma unroll
        for (int mf = 0; mf < 2; mf++) {
            const uint32_t* p = ab + mf * 16 * asr + kst * 8;
            a[mf][0] = p[0]; a[mf][1] = p[8 * asr];
            a[mf][2] = p[4]; a[mf][3] = p[8 * asr + 4];
        }
        #pragma unroll
        for (int nf = 0; nf < 4; nf++) {
            const uint32_t* p = bb + nf * 8 * bsr + kst * 8;
            b[nf][0] = p[0]; b[nf][1] = p[4];
        }
        #pragma unroll
        for (int mf = 0; mf < 2; mf++)
            #pragma unroll
            for (int nf = 0; nf < 4; nf++)
                mma_tf32(acc[mf][nf], a[mf], b[nf]);
    }
}

// ---------------- tf32 rounding kernel (weights) ----------------
__global__ void round_kernel(const float* __restrict__ in, float* __restrict__ out, int n4) {
    for (int i = blockIdx.x * blockDim.x + threadIdx.x; i < n4; i += gridDim.x * blockDim.x) {
        float4 v = ((const float4*)in)[i];
        v.x = rndtf(v.x); v.y = rndtf(v.y); v.z = rndtf(v.z); v.w = rndtf(v.w);
        ((float4*)out)[i] = v;
    }
}

// ======================= mma.sync tf32 NT GEMM (3-stage) =======================
#define PADK   36
#define STGF   (128 * PADK)
#define STAGEF (2 * STGF)
#define GSMEM  (3 * STAGEF * 4)        // 110592 bytes

__device__ __forceinline__ void load_stage(uint32_t sbase, int buf, int si,
                                           const float* __restrict__ A,
                                           const float* __restrict__ B,
                                           int lda, int ldb, int tid) {
    uint32_t as = sbase + (uint32_t)buf * (STAGEF * 4);
    uint32_t bs = as + STGF * 4;
    #pragma unroll
    for (int it = 0; it < 4; it++) {
        int idx = tid + it * 256;
        int m = idx >> 3, kq = idx & 7;
        uint32_t off = (uint32_t)(m * PADK + kq * 4) * 4;
        CPA16(as + off, A + (size_t)m * lda + si * 32 + kq * 4);
        CPA16(bs + off, B + (size_t)m * ldb + si * 32 + kq * 4);
    }
    CPCOMMIT();
}

__global__ void __launch_bounds__(256, 2)
tc_gemm_nt(const float* __restrict__ A, int lda, long long sAz,
           const float* __restrict__ B, int ldb, long long sBz,
           float* __restrict__ C, int ldc, long long sCz,
           const float* __restrict__ bias, const float* __restrict__ res,
           int K, int round_c) {
    extern __shared__ float smf[];
    uint32_t sb = smem_u32(smf);
    A += (long long)blockIdx.z * sAz + (size_t)blockIdx.y * 128 * lda;
    B += (long long)blockIdx.z * sBz + (size_t)blockIdx.x * 128 * ldb;
    C += (long long)blockIdx.z * sCz;
    const int m0 = blockIdx.y * 128, n0 = blockIdx.x * 128;
    const int tid = threadIdx.x;
    const int lane = tid & 31, wid = tid >> 5;
    const int wm = wid & 3, wn = wid >> 2;
    const int r = lane >> 2, kg = lane & 3;

    float acc[2][8][4];
    #pragma unroll
    for (int mf = 0; mf < 2; mf++)
        #pragma unroll
        for (int nf = 0; nf < 8; nf++)
            #pragma unroll
            for (int i = 0; i < 4; i++) acc[mf][nf][i] = 0.f;

    const int nk = K >> 5;
    load_stage(sb, 0, 0, A, B, lda, ldb, tid);
    load_stage(sb, 1, 1, A, B, lda, ldb, tid);

    for (int s = 0; s < nk; s++) {
        if (s + 1 < nk) {
            asm volatile("cp.async.wait_group 1;" ::: "memory");
        } else {
            asm volatile("cp.async.wait_group 0;" ::: "memory");
        }
        __syncthreads();
        if (s + 2 < nk)
            load_stage(sb, (s + 2) % 3, s + 2, A, B, lda, ldb, tid);

        const uint32_t* as = (const uint32_t*)smf + (s % 3) * STAGEF;
        const uint32_t* bs = as + STGF;
        const uint32_t* abase = as + (wm * 32 + r) * PADK + kg;
        const uint32_t* bbase = bs + (wn * 64 + r) * PADK + kg;
        #pragma unroll
        for (int kst = 0; kst < 4; kst++) {
            uint32_t a[2][4], b[8][2];
            #pragma unroll
            for (int mf = 0; mf < 2; mf++) {
                const uint32_t* p = abase + mf * 16 * PADK + kst * 8;
                a[mf][0] = p[0]; a[mf][1] = p[8 * PADK];
                a[mf][2] = p[4]; a[mf][3] = p[8 * PADK + 4];
            }
            #pragma unroll
            for (int nf = 0; nf < 8; nf++) {
                const uint32_t* p = bbase + nf * 8 * PADK + kst * 8;
                b[nf][0] = p[0]; b[nf][1] = p[4];
            }
            #pragma unroll
            for (int mf = 0; mf < 2; mf++)
                #pragma unroll
                for (int nf = 0; nf < 8; nf++)
                    mma_tf32(acc[mf][nf], a[mf], b[nf]);
        }
    }

    #pragma unroll
    for (int mf = 0; mf < 2; mf++) {
        int row = m0 + wm * 32 + mf * 16 + r;
        #pragma unroll
        for (int half = 0; half < 2; half++) {
            int rr = row + half * 8;
            float* crow = C + (size_t)rr * ldc;
            const float* rrow = res ? res + (size_t)rr * ldc : nullptr;
            #pragma unroll
            for (int nf = 0; nf < 8; nf++) {
                int col = n0 + wn * 64 + nf * 8 + 2 * kg;
                float2 v;
                v.x = acc[mf][nf][half * 2 + 0];
                v.y = acc[mf][nf][half * 2 + 1];
                if (bias) { v.x += bias[col]; v.y += bias[col + 1]; }
                if (rrow) {
                    const float2 rv = *(const float2*)(rrow + col);
                    v.x += rv.x; v.y += rv.y;
                }
                if (round_c) { v.x = rndtf(v.x); v.y = rndtf(v.y); }
                *(float2*)(crow + col) = v;
            }
        }
    }
}

// ---------------- LayerNorm (writes tf32-rounded) ----------------
__global__ void ln_kernel(const float* __restrict__ x, const float* __restrict__ gamma,
                          const float* __restrict__ beta, float* __restrict__ out) {
    int row = blockIdx.x;
    int tid = threadIdx.x;
    const float4 v = ((const float4*)(x + (size_t)row * DD))[tid];
    float s  = v.x + v.y + v.z + v.w;
    float s2 = v.x * v.x + v.y * v.y + v.z * v.z + v.w * v.w;
    __shared__ float red[16];
    s = warp_sum(s); s2 = warp_sum(s2);
    if ((tid & 31) == 0) { red[tid >> 5] = s; red[(tid >> 5) + 8] = s2; }
    __syncthreads();
    float ts = 0.f, ts2 = 0.f;
    #pragma unroll
    for (int i = 0; i < 8; i++) { ts += red[i]; ts2 += red[i + 8]; }
    float mu  = ts / (float)DD;
    float var = ts2 / (float)DD - mu * mu;
    float rstd = 1.0f / sqrtf(var + 1e-5f);
    const float4 gm = ((const float4*)gamma)[tid];
    const float4 bt = ((const float4*)beta)[tid];
    float4 o;
    o.x = rndtf((v.x - mu) * rstd * gm.x + bt.x);
    o.y = rndtf((v.y - mu) * rstd * gm.y + bt.y);
    o.z = rndtf((v.z - mu) * rstd * gm.z + bt.z);
    o.w = rndtf((v.w - mu) * rstd * gm.w + bt.w);
    ((float4*)(out + (size_t)row * DD))[tid] = o;
}

// ---------------- RoPE (writes tf32-rounded) ----------------
__global__ void rope_kernel(float* __restrict__ qkv) {
    int row = blockIdx.x;
    int t = row & (TT_ - 1);
    int h = threadIdx.x >> 5;
    int i = threadIdx.x & 31;
    float invf = expf(-logf(10000.0f) * (2.0f * (float)i) / 64.0f);
    float ang = (float)t * invf;
    float s, c;
    sincosf(ang, &s, &c);
    float* p = qkv + (size_t)row * 3072 + h * 64;
    float x1 = p[i], x2 = p[i + 32];
    p[i]      = rndtf(x1 * c - x2 * s);
    p[i + 32] = rndtf(x2 * c + x1 * s);
    float* pk = p + 1024;
    x1 = pk[i]; x2 = pk[i + 32];
    pk[i]      = rndtf(x1 * c - x2 * s);
    pk[i + 32] = rndtf(x2 * c + x1 * s);
}

// ====== fused causal scores + softmax + probs-write + PV -> ctx ======
// smem: Qs[128][68], Ks[2][64][68], Vr[2][64][68], Ss[128][68], Red/RowM/RowI
#define ATTN_SMEM ((8704 + 8704 + 8704 + 8704 + 768) * 4)

__device__ __forceinline__ void tile_load64(uint32_t dst, const float* __restrict__ src, int tid) {
    #pragma unroll
    for (int it = 0; it < 4; it++) {
        int idx = tid + it * 256;
        int row = idx >> 4, c4 = (idx & 15) * 4;
        CPA16(dst + (uint32_t)(row * 68 + c4) * 4, src + (size_t)row * 3072 + c4);
    }
}

__global__ void __launch_bounds__(256, 1)
attn_kernel(const float* __restrict__ qkv2, float* __restrict__ probs,
            float* __restrict__ ctx) {
    extern __shared__ uint32_t smu[];
    uint32_t* Qs = smu;                     // 8704
    uint32_t* Ks = smu + 8704;              // 2 x 4352
    uint32_t* Vr = smu + 17408;             // 2 x 4352
    float*    Ss = (float*)(smu + 26112);   // 8704
    float*    Red  = (float*)(smu + 34816); // 512
    float*    RowM = Red + 512;
    float*    RowI = RowM + 128;
    uint32_t sb = smem_u32(smu);
    const uint32_t KsB = sb + 8704 * 4;
    const uint32_t VrB = sb + 17408 * 4;

    const int bh = blockIdx.x, tq = blockIdx.y;
    const int b = bh >> 4, h = bh & 15;
    const int tid = threadIdx.x, lane = tid & 31, wid = tid >> 5;
    const int wm = wid & 3, wn = wid >> 2;
    const int r = lane >> 2, kg = lane & 3;
    const int jmax = 2 * tq + 2;

    const float* qptr  = qkv2 + ((size_t)(b * TT_ + tq * 128)) * 3072 + h * 64;
    const float* kbase = qkv2 + ((size_t)(b * TT_)) * 3072 + 1024 + h * 64;
    const float* vbase = qkv2 + ((size_t)(b * TT_)) * 3072 + 2048 + h * 64;

    // prologue: Q + K0 in one group
    #pragma unroll
    for (int it = 0; it < 8; it++) {
        int idx = tid + it * 256;
        int row = idx >> 4, c4 = (idx & 15) * 4;
        CPA16(sb + (uint32_t)(row * 68 + c4) * 4, qptr + (size_t)row * 3072 + c4);
    }
    tile_load64(KsB, kbase, tid);
    CPCOMMIT();

    int rowg[2][2];
    float m_[2][2], s_[2][2], rM[2][2], rI[2][2];
    #pragma unroll
    for (int mf = 0; mf < 2; mf++)
        #pragma unroll
        for (int hf = 0; hf < 2; hf++) {
            rowg[mf][hf] = tq * 128 + wm * 32 + mf * 16 + hf * 8 + r;
            m_[mf][hf] = -1e30f; s_[mf][hf] = 0.f;
        }

    float acc[2][4][4];

    // ---------- Pass 1: stats ----------
    for (int j = 0; j < jmax; j++) {
        if (j + 1 < jmax) {
            tile_load64(KsB + ((j + 1) & 1) * 4352 * 4, kbase + (size_t)(j + 1) * 64 * 3072, tid);
            CPCOMMIT();
            asm volatile("cp.async.wait_group 1;" ::: "memory");
        } else {
            asm volatile("cp.async.wait_group 0;" ::: "memory");
        }
        __syncthreads();
        mma_tile(Qs, 68, Ks + (j & 1) * 4352, 68, wm, wn, r, kg, acc);

        const bool needmask = (j >= 2 * tq);
        const int colbase = j * 64 + wn * 32;
        #pragma unroll
        for (int mf = 0; mf < 2; mf++)
            #pragma unroll
            for (int hf = 0; hf < 2; hf++) {
                float vmax = -1e30f;
                #pragma unroll
                for (int nf = 0; nf < 4; nf++)
                    #pragma unroll
                    for (int c = 0; c < 2; c++) {
                        float v = acc[mf][nf][hf * 2 + c] * 0.125f;
                        if (needmask && (colbase + nf * 8 + 2 * kg + c) > rowg[mf][hf])
                            v = -1e30f;
                        acc[mf][nf][hf * 2 + c] = v;
                        vmax = fmaxf(vmax, v);
                    }
                if (vmax > -1e30f) {
                    float mo = m_[mf][hf];
                    float mn = fmaxf(mo, vmax);
                    float ts = 0.f;
                    #pragma unroll
                    for (int nf = 0; nf < 4; nf++)
                        #pragma unroll
                        for (int c = 0; c < 2; c++)
                            ts += __expf(acc[mf][nf][hf * 2 + c] - mn);
                    s_[mf][hf] = s_[mf][hf] * __expf(mo - mn) + ts;
                    m_[mf][hf] = mn;
                }
            }
        __syncthreads();
    }

    // reduce lanes sharing a row
    #pragma unroll
    for (int mf = 0; mf < 2; mf++)
        #pragma unroll
        for (int hf = 0; hf < 2; hf++) {
            float m = m_[mf][hf], s = s_[mf][hf];
            #pragma unroll
            for (int o = 1; o <= 2; o <<= 1) {
                float om = __shfl_xor_sync(0xffffffffu, m, o);
                float os = __shfl_xor_sync(0xffffffffu, s, o);
                float mn = fmaxf(m, om);
                s = s * __expf(m - mn) + os * __expf(om - mn);
                m = mn;
            }
            m_[mf][hf] = m; s_[mf][hf] = s;
        }
    if (kg == 0) {
        #pragma unroll
        for (int mf = 0; mf < 2; mf++)
            #pragma unroll
            for (int hf = 0; hf < 2; hf++) {
                int rl = wm * 32 + mf * 16 + hf * 8 + r;
                Red[(wn * 128 + rl) * 2 + 0] = m_[mf][hf];
                Red[(wn * 128 + rl) * 2 + 1] = s_[mf][hf];
            }
    }
    __syncthreads();
    if (tid < 128) {
        float m0 = Red[tid * 2], s0 = Red[tid * 2 + 1];
        float m1 = Red[(128 + tid) * 2], s1 = Red[(128 + tid) * 2 + 1];
        float mn = fmaxf(m0, m1);
        float st = s0 * __expf(m0 - mn) + s1 * __expf(m1 - mn);
        RowM[tid] = mn;
        RowI[tid] = 1.0f / st;
    }
    __syncthreads();
    #pragma unroll
    for (int mf = 0; mf < 2; mf++)
        #pragma unroll
        for (int hf = 0; hf < 2; hf++) {
            int rl = wm * 32 + mf * 16 + hf * 8 + r;
            rM[mf][hf] = RowM[rl];
            rI[mf][hf] = RowI[rl];
        }

    // ---------- Pass 2: recompute + write probs + PV accumulate ----------
    float acc_o[2][4][4];
    #pragma unroll
    for (int mf = 0; mf < 2; mf++)
        #pragma unroll
        for (int nf = 0; nf < 4; nf++)
            #pragma unroll
            for (int i = 0; i < 4; i++) acc_o[mf][nf][i] = 0.f;

    __syncthreads();
    tile_load64(KsB, kbase, tid);
    tile_load64(VrB, vbase, tid);
    CPCOMMIT();

    for (int j = 0; j < jmax; j++) {
        __syncthreads();   // prior iter's Ss/Vr readers done
        if (j + 1 < jmax) {
            tile_load64(KsB + ((j + 1) & 1) * 4352 * 4, kbase + (size_t)(j + 1) * 64 * 3072, tid);
            tile_load64(VrB + ((j + 1) & 1) * 4352 * 4, vbase + (size_t)(j + 1) * 64 * 3072, tid);
            CPCOMMIT();
            asm volatile("cp.async.wait_group 1;" ::: "memory");
        } else {
            asm volatile("cp.async.wait_group 0;" ::: "memory");
        }
        __syncthreads();
        mma_tile(Qs, 68, Ks + (j & 1) * 4352, 68, wm, wn, r, kg, acc);

        const bool needmask = (j >= 2 * tq);
        const int colbase = j * 64 + wn * 32;
        #pragma unroll
        for (int mf = 0; mf < 2; mf++)
            #pragma unroll
            for (int hf = 0; hf < 2; hf++) {
                int rl = wm * 32 + mf * 16 + hf * 8 + r;
                #pragma unroll
                for (int nf = 0; nf < 4; nf++)
                    #pragma unroll
                    for (int c = 0; c < 2; c++) {
                        int coll = wn * 32 + nf * 8 + 2 * kg + c;
                        float p = 0.f;
                        if (!(needmask && (colbase + nf * 8 + 2 * kg + c) > rowg[mf][hf]))
                            p = __expf(acc[mf][nf][hf * 2 + c] * 0.125f - rM[mf][hf]) * rI[mf][hf];
                        Ss[rl * 68 + coll] = p;
                    }
            }
        __syncthreads();   // Ss ready (Vr(j) already arrived)

        // write probs from Ss
        #pragma unroll
        for (int it = 0; it < 8; it++) {
            int idx = tid + it * 256;
            int rl = idx >> 4, c4 = (idx & 15) * 4;
            float4 v = *(const float4*)(Ss + rl * 68 + c4);
            *(float4*)(probs + ((size_t)bh * TT_ + tq * 128 + rl) * TT_ + j * 64 + c4) = v;
        }

        // PV mma: acc_o += tf32(Ss) x V^T (transposed read from Vr)
        const uint32_t* vb = Vr + (j & 1) * 4352;
        const float* abp = Ss + (wm * 32 + r) * 68 + kg;
        #pragma unroll
        for (int kst = 0; kst < 8; kst++) {
            uint32_t a[2][4], bfr[4][2];
            #pragma unroll
            for (int mf = 0; mf < 2; mf++) {
                const float* p = abp + mf * 16 * 68 + kst * 8;
                a[mf][0] = f2tf(p[0]); a[mf][1] = f2tf(p[8 * 68]);
                a[mf][2] = f2tf(p[4]); a[mf][3] = f2tf(p[8 * 68 + 4]);
            }
            #pragma unroll
            for (int nf = 0; nf < 4; nf++) {
                int nidx = wn * 32 + nf * 8 + r;
                bfr[nf][0] = vb[(kst * 8 + kg) * 68 + nidx];
                bfr[nf][1] = vb[(kst * 8 + kg + 4) * 68 + nidx];
            }
            #pragma unroll
            for (int mf = 0; mf < 2; mf++)
                #pragma unroll
                for (int nf = 0; nf < 4; nf++)
                    mma_tf32(acc_o[mf][nf], a[mf], bfr[nf]);
        }
    }

    // zero-fill probs cols [jmax*64, 2048)
    int zstart = jmax * 64;
    float4 z = make_float4(0.f, 0.f, 0.f, 0.f);
    for (int rl = wid; rl < 128; rl += 8) {
        float* dst = probs + ((size_t)bh * TT_ + tq * 128 + rl) * TT_;
        for (int c = zstart + lane * 4; c < TT_; c += 128)
            *(float4*)(dst + c) = z;
    }

    // ctx epilogue (tf32-rounded for next GEMM)
    #pragma unroll
    for (int mf = 0; mf < 2; mf++)
        #pragma unroll
        for (int hf = 0; hf < 2; hf++) {
            int row = b * TT_ + tq * 128 + wm * 32 + mf * 16 + hf * 8 + r;
            float* crow = ctx + (size_t)row * DD + h * 64;
            #pragma unroll
            for (int nf = 0; nf < 4; nf++) {
                int col = wn * 32 + nf * 8 + 2 * kg;
                float2 v;
                v.x = rndtf(acc_o[mf][nf][hf * 2 + 0]);
                v.y = rndtf(acc_o[mf][nf][hf * 2 + 1]);
                *(float2*)(crow + col) = v;
            }
        }
}

// ---------------- Launch ----------------
extern "C" void kernel_launch(void* const* d_in, const int* in_sizes, int n_in,
                              void* d_out, int out_size) {
    const float* x      = (const float*)d_in[0];
    const float* w_in   = (const float*)d_in[1];
    const float* b_in   = (const float*)d_in[2];
    const float* w_out  = (const float*)d_in[3];
    const float* b_out  = (const float*)d_in[4];
    const float* gamma  = (const float*)d_in[5];
    const float* beta   = (const float*)d_in[6];
    float* out = (float*)d_out;

    float *xn, *qkv, *qkv2, *ctx, *scores, *wr_in, *wr_out;
    cudaGetSymbolAddress((void**)&xn, g_xn);
    cudaGetSymbolAddress((void**)&qkv, g_qkv);
    cudaGetSymbolAddress((void**)&qkv2, g_qkv2);
    cudaGetSymbolAddress((void**)&ctx, g_ctx);
    cudaGetSymbolAddress((void**)&scores, g_scores);
    cudaGetSymbolAddress((void**)&wr_in, g_wr_in);
    cudaGetSymbolAddress((void**)&wr_out, g_wr_out);

    cudaFuncSetAttribute(tc_gemm_nt, cudaFuncAttributeMaxDynamicSharedMemorySize, GSMEM);
    cudaFuncSetAttribute(attn_kernel, cudaFuncAttributeMaxDynamicSharedMemorySize, ATTN_SMEM);

    bool has_attn = ((long long)out_size >= (long long)BTD + BHTT);
    float* probs = has_attn ? (out + BTD) : scores;

    // 0. round weights to tf32 patterns
    round_kernel<<<1024, 256>>>(w_in, wr_in, 3 * DD * DD / 4);
    round_kernel<<<512, 256>>>(w_out, wr_out, DD * DD / 4);
    // 1. pre-LN (tf32-rounded output)
    ln_kernel<<<ROWS, 256>>>(x, gamma, beta, xn);
    // 2. fused QKV projection (+bias), rounded output
    tc_gemm_nt<<<dim3(24, 32, 1), 256, GSMEM>>>(xn, 1024, 0,
                                                wr_in, 1024, 0,
                                                qkv, 3072, 0,
                                                b_in, nullptr, 1024, 1);
    // 3. RoPE on q,k (in place, rounded)
    rope_kernel<<<ROWS, 512>>>(qkv);
    // 4. second projection, z-batched, rounded output
    tc_gemm_nt<<<dim3(8, 32, 3), 256, GSMEM>>>(qkv, 3072, 1024,
                                               wr_in, 1024, 1048576LL,
                                               qkv2, 3072, 1024,
                                               nullptr, nullptr, 1024, 1);
    // 5-7. fused scores + softmax + probs write + PV
    attn_kernel<<<dim3(32, 16), 256, ATTN_SMEM>>>(qkv2, probs, ctx);
    // 8. out projection + bias + residual (fp32 output)
    tc_gemm_nt<<<dim3(8, 32, 1), 256, GSMEM>>>(ctx, 1024, 0,
                                               wr_out, 1024, 0,
                                               out, 1024, 0,
                                               b_out, x, 1024, 0);
}

// round 10
// speedup vs baseline: 3.3497x; 1.1297x over previous
#include <cuda_runtime.h>
#include <cstdint>

// Problem constants
#define BB   2
#define TT_  2048
#define DD   1024
#define HH   16
#define ROWS (BB * TT_)               // 4096
#define BTD  (ROWS * DD)              // 4194304
#define BHTT 134217728LL              // B*H*T*T

// Scratch (allocation-free rule: __device__ globals)
__device__ float g_xn[ROWS * DD];
__device__ float g_qkv[ROWS * 3 * DD];
__device__ float g_qkv2[ROWS * 3 * DD];
__device__ float g_ctx[ROWS * DD];
__device__ float g_wr_in[3 * DD * DD];
__device__ float g_wr_out[DD * DD];
__device__ float g_scores[134217728ULL];   // fallback probs

__device__ __forceinline__ float warp_sum(float v) {
    #pragma unroll
    for (int o = 16; o; o >>= 1) v += __shfl_xor_sync(0xffffffffu, v, o);
    return v;
}
__device__ __forceinline__ uint32_t smem_u32(const void* p) {
    uint32_t a;
    asm("{ .reg .u64 t; cvta.to.shared.u64 t, %1; cvt.u32.u64 %0, t; }" : "=r"(a) : "l"(p));
    return a;
}
__device__ __forceinline__ uint32_t f2tf(float x) {
    uint32_t r;
    asm("cvt.rna.tf32.f32 %0, %1;" : "=r"(r) : "f"(x));
    return r;
}
__device__ __forceinline__ float rndtf(float x) { return __uint_as_float(f2tf(x)); }

__device__ __forceinline__ void mma_tf32(float* c, const uint32_t* a, const uint32_t* b) {
    asm volatile(
        "mma.sync.aligned.m16n8k8.row.col.f32.tf32.tf32.f32 "
        "{%0,%1,%2,%3}, {%4,%5,%6,%7}, {%8,%9}, {%0,%1,%2,%3};"
        : "+f"(c[0]), "+f"(c[1]), "+f"(c[2]), "+f"(c[3])
        : "r"(a[0]), "r"(a[1]), "r"(a[2]), "r"(a[3]), "r"(b[0]), "r"(b[1]));
}
__device__ __forceinline__ void ldsm4(uint32_t* d, uint32_t addr) {
    asm volatile("ldmatrix.sync.aligned.m8n8.x4.shared.b16 {%0,%1,%2,%3}, [%4];"
                 : "=r"(d[0]), "=r"(d[1]), "=r"(d[2]), "=r"(d[3]) : "r"(addr));
}

#define CPA16(dst, src) \
    asm volatile("cp.async.cg.shared.global [%0], [%1], 16;" :: "r"(dst), "l"(src) : "memory")
#define CPCOMMIT() asm volatile("cp.async.commit_group;" ::: "memory")

// ---------------- tf32 rounding kernel (weights) ----------------
__global__ void round_kernel(const float* __restrict__ in, float* __restrict__ out, int n4) {
    for (int i = blockIdx.x * blockDim.x + threadIdx.x; i < n4; i += gridDim.x * blockDim.x) {
        float4 v = ((const float4*)in)[i];
        v.x = rndtf(v.x); v.y = rndtf(v.y); v.z = rndtf(v.z); v.w = rndtf(v.w);
        ((float4*)out)[i] = v;
    }
}

// ============ mma.sync tf32 NT GEMM: 128x128 CTA, 4 warps (64x64/warp), ldmatrix ============
#define PADK   36
#define STGF   (128 * PADK)
#define STAGEF (2 * STGF)
#define GSMEM  (3 * STAGEF * 4)        // 110592 bytes

__device__ __forceinline__ void load_stage(uint32_t sbase, int buf, int si,
                                           const float* __restrict__ A,
                                           const float* __restrict__ B,
                                           int lda, int ldb, int tid) {
    uint32_t as = sbase + (uint32_t)buf * (STAGEF * 4);
    uint32_t bs = as + STGF * 4;
    #pragma unroll
    for (int it = 0; it < 8; it++) {
        int idx = tid + it * 128;
        int m = idx >> 3, kq = idx & 7;
        uint32_t off = (uint32_t)(m * PADK + kq * 4) * 4;
        CPA16(as + off, A + (size_t)m * lda + si * 32 + kq * 4);
        CPA16(bs + off, B + (size_t)m * ldb + si * 32 + kq * 4);
    }
    CPCOMMIT();
}

__global__ void __launch_bounds__(128, 2)
tc_gemm_nt(const float* __restrict__ A, int lda, long long sAz,
           const float* __restrict__ B, int ldb, long long sBz,
           float* __restrict__ C, int ldc, long long sCz,
           const float* __restrict__ bias, const float* __restrict__ res,
           int K, int round_c) {
    extern __shared__ float smf[];
    uint32_t sb = smem_u32(smf);
    A += (long long)blockIdx.z * sAz + (size_t)blockIdx.y * 128 * lda;
    B += (long long)blockIdx.z * sBz + (size_t)blockIdx.x * 128 * ldb;
    C += (long long)blockIdx.z * sCz;
    const int m0 = blockIdx.y * 128, n0 = blockIdx.x * 128;
    const int tid = threadIdx.x;
    const int lane = tid & 31, wid = tid >> 5;
    const int wm = wid & 1, wn = wid >> 1;        // 2x2 warps, 64x64 tile each
    const int r = lane >> 2, kg = lane & 3;

    // ldmatrix per-thread offsets (element units)
    const int arowt = (lane & 7) + ((lane >> 3) & 1) * 8;
    const int acolt = ((lane >> 4) & 1) * 4;
    const int browt = (lane & 7) + ((lane >> 4) & 1) * 8;
    const int bcolt = ((lane >> 3) & 1) * 4;
    const uint32_t aoff = (uint32_t)(((wm * 64 + arowt) * PADK + acolt) * 4);
    const uint32_t boff = (uint32_t)(((wn * 64 + browt) * PADK + bcolt) * 4) + STGF * 4;

    float acc[4][8][4];
    #pragma unroll
    for (int mf = 0; mf < 4; mf++)
        #pragma unroll
        for (int nf = 0; nf < 8; nf++)
            #pragma unroll
            for (int i = 0; i < 4; i++) acc[mf][nf][i] = 0.f;

    const int nk = K >> 5;
    load_stage(sb, 0, 0, A, B, lda, ldb, tid);
    load_stage(sb, 1, 1, A, B, lda, ldb, tid);

    for (int s = 0; s < nk; s++) {
        if (s + 1 < nk) {
            asm volatile("cp.async.wait_group 1;" ::: "memory");
        } else {
            asm volatile("cp.async.wait_group 0;" ::: "memory");
        }
        __syncthreads();
        if (s + 2 < nk)
            load_stage(sb, (s + 2) % 3, s + 2, A, B, lda, ldb, tid);

        const uint32_t stg = sb + (uint32_t)(s % 3) * (STAGEF * 4);
        const uint32_t aad = stg + aoff;
        const uint32_t bad = stg + boff;
        #pragma unroll
        for (int kst = 0; kst < 4; kst++) {
            uint32_t a[4][4], b[4][4];
            #pragma unroll
            for (int mf = 0; mf < 4; mf++)
                ldsm4(a[mf], aad + mf * (16 * PADK * 4) + kst * 32);
            #pragma unroll
            for (int p = 0; p < 4; p++)
                ldsm4(b[p], bad + p * (16 * PADK * 4) + kst * 32);
            #pragma unroll
            for (int mf = 0; mf < 4; mf++)
                #pragma unroll
                for (int p = 0; p < 4; p++) {
                    mma_tf32(acc[mf][2 * p + 0], a[mf], &b[p][0]);
                    mma_tf32(acc[mf][2 * p + 1], a[mf], &b[p][2]);
                }
        }
    }

    #pragma unroll
    for (int mf = 0; mf < 4; mf++) {
        #pragma unroll
        for (int half = 0; half < 2; half++) {
            int rr = m0 + wm * 64 + mf * 16 + half * 8 + r;
            float* crow = C + (size_t)rr * ldc;
            const float* rrow = res ? res + (size_t)rr * ldc : nullptr;
            #pragma unroll
            for (int nf = 0; nf < 8; nf++) {
                int col = n0 + wn * 64 + nf * 8 + 2 * kg;
                float2 v;
                v.x = acc[mf][nf][half * 2 + 0];
                v.y = acc[mf][nf][half * 2 + 1];
                if (bias) { v.x += bias[col]; v.y += bias[col + 1]; }
                if (rrow) {
                    const float2 rv = *(const float2*)(rrow + col);
                    v.x += rv.x; v.y += rv.y;
                }
                if (round_c) { v.x = rndtf(v.x); v.y = rndtf(v.y); }
                *(float2*)(crow + col) = v;
            }
        }
    }
}

// ---------------- LayerNorm (writes tf32-rounded) ----------------
__global__ void ln_kernel(const float* __restrict__ x, const float* __restrict__ gamma,
                          const float* __restrict__ beta, float* __restrict__ out) {
    int row = blockIdx.x;
    int tid = threadIdx.x;
    const float4 v = ((const float4*)(x + (size_t)row * DD))[tid];
    float s  = v.x + v.y + v.z + v.w;
    float s2 = v.x * v.x + v.y * v.y + v.z * v.z + v.w * v.w;
    __shared__ float red[16];
    s = warp_sum(s); s2 = warp_sum(s2);
    if ((tid & 31) == 0) { red[tid >> 5] = s; red[(tid >> 5) + 8] = s2; }
    __syncthreads();
    float ts = 0.f, ts2 = 0.f;
    #pragma unroll
    for (int i = 0; i < 8; i++) { ts += red[i]; ts2 += red[i + 8]; }
    float mu  = ts / (float)DD;
    float var = ts2 / (float)DD - mu * mu;
    float rstd = 1.0f / sqrtf(var + 1e-5f);
    const float4 gm = ((const float4*)gamma)[tid];
    const float4 bt = ((const float4*)beta)[tid];
    float4 o;
    o.x = rndtf((v.x - mu) * rstd * gm.x + bt.x);
    o.y = rndtf((v.y - mu) * rstd * gm.y + bt.y);
    o.z = rndtf((v.z - mu) * rstd * gm.z + bt.z);
    o.w = rndtf((v.w - mu) * rstd * gm.w + bt.w);
    ((float4*)(out + (size_t)row * DD))[tid] = o;
}

// ---------------- RoPE (writes tf32-rounded) ----------------
__global__ void rope_kernel(float* __restrict__ qkv) {
    int row = blockIdx.x;
    int t = row & (TT_ - 1);
    int h = threadIdx.x >> 5;
    int i = threadIdx.x & 31;
    float invf = expf(-logf(10000.0f) * (2.0f * (float)i) / 64.0f);
    float ang = (float)t * invf;
    float s, c;
    sincosf(ang, &s, &c);
    float* p = qkv + (size_t)row * 3072 + h * 64;
    float x1 = p[i], x2 = p[i + 32];
    p[i]      = rndtf(x1 * c - x2 * s);
    p[i + 32] = rndtf(x2 * c + x1 * s);
    float* pk = p + 1024;
    x1 = pk[i]; x2 = pk[i + 32];
    pk[i]      = rndtf(x1 * c - x2 * s);
    pk[i + 32] = rndtf(x2 * c + x1 * s);
}

// ====== fused causal scores + softmax (fixed max) + probs-write + PV -> ctx ======
// smem words: Qs 8704 | Ks 4352 | Vr 4352 | Ss 8704 | Red 256 | RowI 128 = 105984 B
#define ATTN_SMEM ((8704 + 4352 + 4352 + 8704 + 256 + 128) * 4)

__device__ __forceinline__ void tile_load64(uint32_t dst, const float* __restrict__ src, int tid) {
    #pragma unroll
    for (int it = 0; it < 4; it++) {
        int idx = tid + it * 256;
        int row = idx >> 4, c4 = (idx & 15) * 4;
        CPA16(dst + (uint32_t)(row * 68 + c4) * 4, src + (size_t)row * 3072 + c4);
    }
}

__global__ void __launch_bounds__(256, 2)
attn_kernel(const float* __restrict__ qkv2, float* __restrict__ probs,
            float* __restrict__ ctx) {
    extern __shared__ uint32_t smu[];
    uint32_t* Ks = smu + 8704;
    uint32_t* Vr = smu + 13056;
    float*    Ss = (float*)(smu + 17408);
    float*    Red  = (float*)(smu + 26112);   // 256
    float*    RowI = Red + 256;               // 128
    uint32_t sb = smem_u32(smu);
    const uint32_t QsB = sb;
    const uint32_t KsB = sb + 8704 * 4;
    const uint32_t VrB = sb + 13056 * 4;
    const uint32_t SsB = sb + 17408 * 4;

    const int bh = blockIdx.x, tq = blockIdx.y;
    const int b = bh >> 4, h = bh & 15;
    const int tid = threadIdx.x, lane = tid & 31, wid = tid >> 5;
    const int wm = wid & 3, wn = wid >> 2;     // 4m x 2n warps, 32x32 tiles
    const int r = lane >> 2, kg = lane & 3;
    const int jmax = 2 * tq + 2;

    // ldmatrix per-thread offsets
    const int arowt = (lane & 7) + ((lane >> 3) & 1) * 8;
    const int acolt = ((lane >> 4) & 1) * 4;
    const int browt = (lane & 7) + ((lane >> 4) & 1) * 8;
    const int bcolt = ((lane >> 3) & 1) * 4;
    const uint32_t qa = QsB + (uint32_t)(((wm * 32 + arowt) * 68 + acolt) * 4);
    const uint32_t kb = KsB + (uint32_t)(((wn * 32 + browt) * 68 + bcolt) * 4);
    const uint32_t sa = SsB + (uint32_t)(((wm * 32 + arowt) * 68 + acolt) * 4);

    const float* qptr  = qkv2 + ((size_t)(b * TT_ + tq * 128)) * 3072 + h * 64;
    const float* kbase = qkv2 + ((size_t)(b * TT_)) * 3072 + 1024 + h * 64;
    const float* vbase = qkv2 + ((size_t)(b * TT_)) * 3072 + 2048 + h * 64;

    // prologue: Q tile async
    #pragma unroll
    for (int it = 0; it < 8; it++) {
        int idx = tid + it * 256;
        int row = idx >> 4, c4 = (idx & 15) * 4;
        CPA16(QsB + (uint32_t)(row * 68 + c4) * 4, qptr + (size_t)row * 3072 + c4);
    }

    int rowg[2][2];
    float s_[2][2], rI[2][2];
    #pragma unroll
    for (int mf = 0; mf < 2; mf++)
        #pragma unroll
        for (int hf = 0; hf < 2; hf++) {
            rowg[mf][hf] = tq * 128 + wm * 32 + mf * 16 + hf * 8 + r;
            s_[mf][hf] = 0.f;
        }

    float acc[2][4][4];

    // ---------- Pass 1: row sums of exp(score) (fixed max = 0) ----------
    for (int j = 0; j < jmax; j++) {
        __syncthreads();                       // prior mma done reading Ks
        tile_load64(KsB, kbase + (size_t)j * 64 * 3072, tid);
        CPCOMMIT();
        asm volatile("cp.async.wait_group 0;" ::: "memory");
        __syncthreads();

        // QK mma via ldmatrix
        #pragma unroll
        for (int mf = 0; mf < 2; mf++)
            #pragma unroll
            for (int nf = 0; nf < 4; nf++)
                #pragma unroll
                for (int i = 0; i < 4; i++) acc[mf][nf][i] = 0.f;
        #pragma unroll
        for (int kst = 0; kst < 8; kst++) {
            uint32_t a[2][4], bq[2][4];
            ldsm4(a[0], qa + kst * 32);
            ldsm4(a[1], qa + 16 * 68 * 4 + kst * 32);
            ldsm4(bq[0], kb + kst * 32);
            ldsm4(bq[1], kb + 16 * 68 * 4 + kst * 32);
            #pragma unroll
            for (int mf = 0; mf < 2; mf++)
                #pragma unroll
                for (int p = 0; p < 2; p++) {
                    mma_tf32(acc[mf][2 * p + 0], a[mf], &bq[p][0]);
                    mma_tf32(acc[mf][2 * p + 1], a[mf], &bq[p][2]);
                }
        }

        const bool needmask = (j >= 2 * tq);
        const int colbase = j * 64 + wn * 32;
        #pragma unroll
        for (int mf = 0; mf < 2; mf++)
            #pragma unroll
            for (int hf = 0; hf < 2; hf++) {
                float ts = 0.f;
                #pragma unroll
                for (int nf = 0; nf < 4; nf++)
                    #pragma unroll
                    for (int c = 0; c < 2; c++) {
                        float e = __expf(acc[mf][nf][hf * 2 + c] * 0.125f);
                        if (needmask && (colbase + nf * 8 + 2 * kg + c) > rowg[mf][hf])
                            e = 0.f;
                        ts += e;
                    }
                s_[mf][hf] += ts;
            }
    }

    // lane reduce (kg lanes share a row), then cross-warp (wn) via smem
    #pragma unroll
    for (int mf = 0; mf < 2; mf++)
        #pragma unroll
        for (int hf = 0; hf < 2; hf++) {
            float s = s_[mf][hf];
            s += __shfl_xor_sync(0xffffffffu, s, 1);
            s += __shfl_xor_sync(0xffffffffu, s, 2);
            s_[mf][hf] = s;
        }
    if (kg == 0) {
        #pragma unroll
        for (int mf = 0; mf < 2; mf++)
            #pragma unroll
            for (int hf = 0; hf < 2; hf++) {
                int rl = wm * 32 + mf * 16 + hf * 8 + r;
                Red[wn * 128 + rl] = s_[mf][hf];
            }
    }
    __syncthreads();
    if (tid < 128) RowI[tid] = 1.0f / (Red[tid] + Red[128 + tid]);
    __syncthreads();
    #pragma unroll
    for (int mf = 0; mf < 2; mf++)
        #pragma unroll
        for (int hf = 0; hf < 2; hf++)
            rI[mf][hf] = RowI[wm * 32 + mf * 16 + hf * 8 + r];

    // ---------- Pass 2: recompute + normalize + write probs + PV ----------
    float acc_o[2][4][4];
    #pragma unroll
    for (int mf = 0; mf < 2; mf++)
        #pragma unroll
        for (int nf = 0; nf < 4; nf++)
            #pragma unroll
            for (int i = 0; i < 4; i++) acc_o[mf][nf][i] = 0.f;

    for (int j = 0; j < jmax; j++) {
        __syncthreads();                        // prior readers of Ks/Vr/Ss done
        tile_load64(KsB, kbase + (size_t)j * 64 * 3072, tid);
        tile_load64(VrB, vbase + (size_t)j * 64 * 3072, tid);
        CPCOMMIT();
        asm volatile("cp.async.wait_group 0;" ::: "memory");
        __syncthreads();

        // QK mma
        #pragma unroll
        for (int mf = 0; mf < 2; mf++)
            #pragma unroll
            for (int nf = 0; nf < 4; nf++)
                #pragma unroll
                for (int i = 0; i < 4; i++) acc[mf][nf][i] = 0.f;
        #pragma unroll
        for (int kst = 0; kst < 8; kst++) {
            uint32_t a[2][4], bq[2][4];
            ldsm4(a[0], qa + kst * 32);
            ldsm4(a[1], qa + 16 * 68 * 4 + kst * 32);
            ldsm4(bq[0], kb + kst * 32);
            ldsm4(bq[1], kb + 16 * 68 * 4 + kst * 32);
            #pragma unroll
            for (int mf = 0; mf < 2; mf++)
                #pragma unroll
                for (int p = 0; p < 2; p++) {
                    mma_tf32(acc[mf][2 * p + 0], a[mf], &bq[p][0]);
                    mma_tf32(acc[mf][2 * p + 1], a[mf], &bq[p][2]);
                }
        }

        const bool needmask = (j >= 2 * tq);
        const int colbase = j * 64 + wn * 32;
        #pragma unroll
        for (int mf = 0; mf < 2; mf++)
            #pragma unroll
            for (int hf = 0; hf < 2; hf++) {
                int rl = wm * 32 + mf * 16 + hf * 8 + r;
                #pragma unroll
                for (int nf = 0; nf < 4; nf++) {
                    float2 pv;
                    float e0 = __expf(acc[mf][nf][hf * 2 + 0] * 0.125f) * rI[mf][hf];
                    float e1 = __expf(acc[mf][nf][hf * 2 + 1] * 0.125f) * rI[mf][hf];
                    int c0 = colbase + nf * 8 + 2 * kg;
                    if (needmask && c0 > rowg[mf][hf]) e0 = 0.f;
                    if (needmask && c0 + 1 > rowg[mf][hf]) e1 = 0.f;
                    pv.x = rndtf(e0);
                    pv.y = rndtf(e1);
                    *(float2*)(Ss + rl * 68 + wn * 32 + nf * 8 + 2 * kg) = pv;
                }
            }
        __syncthreads();                        // Ss ready

        // write probs from Ss (coalesced float4)
        #pragma unroll
        for (int it = 0; it < 8; it++) {
            int idx = tid + it * 256;
            int rl = idx >> 4, c4 = (idx & 15) * 4;
            float4 v = *(const float4*)(Ss + rl * 68 + c4);
            *(float4*)(probs + ((size_t)bh * TT_ + tq * 128 + rl) * TT_ + j * 64 + c4) = v;
        }

        // PV mma: A = Ss (ldmatrix), B = Vr (scalar transposed reads)
        #pragma unroll
        for (int kst = 0; kst < 8; kst++) {
            uint32_t a[2][4], bfr[4][2];
            ldsm4(a[0], sa + kst * 32);
            ldsm4(a[1], sa + 16 * 68 * 4 + kst * 32);
            #pragma unroll
            for (int nf = 0; nf < 4; nf++) {
                int nidx = wn * 32 + nf * 8 + r;
                bfr[nf][0] = Vr[(kst * 8 + kg) * 68 + nidx];
                bfr[nf][1] = Vr[(kst * 8 + kg + 4) * 68 + nidx];
            }
            #pragma unroll
            for (int mf = 0; mf < 2; mf++)
                #pragma unroll
                for (int nf = 0; nf < 4; nf++)
                    mma_tf32(acc_o[mf][nf], a[mf], bfr[nf]);
        }
    }

    // zero-fill probs cols [jmax*64, 2048)
    int zstart = jmax * 64;
    float4 z = make_float4(0.f, 0.f, 0.f, 0.f);
    for (int rl = wid; rl < 128; rl += 8) {
        float* dst = probs + ((size_t)bh * TT_ + tq * 128 + rl) * TT_;
        for (int c = zstart + lane * 4; c < TT_; c += 128)
            *(float4*)(dst + c) = z;
    }

    // ctx epilogue (tf32-rounded for next GEMM)
    #pragma unroll
    for (int mf = 0; mf < 2; mf++)
        #pragma unroll
        for (int hf = 0; hf < 2; hf++) {
            int row = b * TT_ + tq * 128 + wm * 32 + mf * 16 + hf * 8 + r;
            float* crow = ctx + (size_t)row * DD + h * 64;
            #pragma unroll
            for (int nf = 0; nf < 4; nf++) {
                int col = wn * 32 + nf * 8 + 2 * kg;
                float2 v;
                v.x = rndtf(acc_o[mf][nf][hf * 2 + 0]);
                v.y = rndtf(acc_o[mf][nf][hf * 2 + 1]);
                *(float2*)(crow + col) = v;
            }
        }
}

// ---------------- Launch ----------------
extern "C" void kernel_launch(void* const* d_in, const int* in_sizes, int n_in,
                              void* d_out, int out_size) {
    const float* x      = (const float*)d_in[0];
    const float* w_in   = (const float*)d_in[1];
    const float* b_in   = (const float*)d_in[2];
    const float* w_out  = (const float*)d_in[3];
    const float* b_out  = (const float*)d_in[4];
    const float* gamma  = (const float*)d_in[5];
    const float* beta   = (const float*)d_in[6];
    float* out = (float*)d_out;

    float *xn, *qkv, *qkv2, *ctx, *scores, *wr_in, *wr_out;
    cudaGetSymbolAddress((void**)&xn, g_xn);
    cudaGetSymbolAddress((void**)&qkv, g_qkv);
    cudaGetSymbolAddress((void**)&qkv2, g_qkv2);
    cudaGetSymbolAddress((void**)&ctx, g_ctx);
    cudaGetSymbolAddress((void**)&scores, g_scores);
    cudaGetSymbolAddress((void**)&wr_in, g_wr_in);
    cudaGetSymbolAddress((void**)&wr_out, g_wr_out);

    cudaFuncSetAttribute(tc_gemm_nt, cudaFuncAttributeMaxDynamicSharedMemorySize, GSMEM);
    cudaFuncSetAttribute(attn_kernel, cudaFuncAttributeMaxDynamicSharedMemorySize, ATTN_SMEM);

    bool has_attn = ((long long)out_size >= (long long)BTD + BHTT);
    float* probs = has_attn ? (out + BTD) : scores;

    // 0. round weights to tf32 patterns
    round_kernel<<<1024, 256>>>(w_in, wr_in, 3 * DD * DD / 4);
    round_kernel<<<512, 256>>>(w_out, wr_out, DD * DD / 4);
    // 1. pre-LN (tf32-rounded output)
    ln_kernel<<<ROWS, 256>>>(x, gamma, beta, xn);
    // 2. fused QKV projection (+bias), rounded output
    tc_gemm_nt<<<dim3(24, 32, 1), 128, GSMEM>>>(xn, 1024, 0,
                                                wr_in, 1024, 0,
                                                qkv, 3072, 0,
                                                b_in, nullptr, 1024, 1);
    // 3. RoPE on q,k (in place, rounded)
    rope_kernel<<<ROWS, 512>>>(qkv);
    // 4. second projection, z-batched, rounded output
    tc_gemm_nt<<<dim3(8, 32, 3), 128, GSMEM>>>(qkv, 3072, 1024,
                                               wr_in, 1024, 1048576LL,
                                               qkv2, 3072, 1024,
                                               nullptr, nullptr, 1024, 1);
    // 5-7. fused scores + softmax + probs write + PV
    attn_kernel<<<dim3(32, 16), 256, ATTN_SMEM>>>(qkv2, probs, ctx);
    // 8. out projection + bias + residual (fp32 output)
    tc_gemm_nt<<<dim3(8, 32, 1), 128, GSMEM>>>(ctx, 1024, 0,
                                               wr_out, 1024, 0,
                                               out, 1024, 0,
                                               b_out, x, 1024, 0);
}